// round 1
// baseline (speedup 1.0000x reference)
#include <cuda_runtime.h>
#include <cstdint>

#define NN 100000
#define EE 400000
#define DD 128

// ---------------- scratch (static device allocations; no cudaMalloc) ----------------
__device__ float g_msgA[(size_t)EE * DD];        // 204.8 MB
__device__ float g_msgB[(size_t)EE * DD];        // 204.8 MB
__device__ float g_gi[(size_t)EE * 3 * DD];      // 614.4 MB
__device__ float g_amsg[(size_t)NN * DD];        // 51.2 MB

// ---------------- helpers ----------------
__device__ __forceinline__ uint32_t f2t(float x) {
    uint32_t r;
    asm("cvt.rna.tf32.f32 %0, %1;" : "=r"(r) : "f"(x));
    return r;
}

__device__ __forceinline__ void mma8(float* d, const uint32_t* a, const uint32_t* b) {
    asm volatile(
        "mma.sync.aligned.m16n8k8.row.col.f32.tf32.tf32.f32 "
        "{%0,%1,%2,%3}, {%4,%5,%6,%7}, {%8,%9}, {%0,%1,%2,%3};"
        : "+f"(d[0]), "+f"(d[1]), "+f"(d[2]), "+f"(d[3])
        : "r"(a[0]), "r"(a[1]), "r"(a[2]), "r"(a[3]), "r"(b[0]), "r"(b[1]));
}

__device__ __forceinline__ float sigm(float x) { return 1.f / (1.f + __expf(-x)); }

// Shared-memory layout constants
#define A_STRIDE 132           // 128 + 4 pad (conflict-free frag loads)
#define W_STRIDE 36            // 32 + 4 pad, [n][k] layout
#define SMEM_MAIN_FLOATS (64 * A_STRIDE + 384 * W_STRIDE)    // 8448 + 13824 = 22272
#define RO_A_STRIDE 260        // 256 + 4
#define RO_W_STRIDE 264        // 256 + 8, [k][n] layout
#define SMEM_RO_FLOATS (64 * RO_A_STRIDE + 32 * RO_W_STRIDE) // 16640 + 8448 = 25088

// ======================================================================
// k_init: n_input = f_edges @ W_edge (fp32, K=32) -> write msg0 (+zero row 0),
//         then gi = n_input @ W_ih^T + b_ih  (tf32 GEMM, BM=64, BN=384, K=128)
// ======================================================================
__global__ __launch_bounds__(256) void k_init(
    const float* __restrict__ f_edges, const float* __restrict__ W_edge,
    const float* __restrict__ W_ih, const float* __restrict__ b_ih,
    float* __restrict__ msg0, float* __restrict__ gi)
{
    extern __shared__ float smem[];
    float* sh_a = smem;                       // 64 x A_STRIDE (n_input tile, fp32)
    float* sh_w = smem + 64 * A_STRIDE;       // 384 x W_STRIDE (W chunk) -- overlaps fe/we
    float* sh_fe = sh_w;                      // 64 x 32
    float* sh_we = sh_fe + 64 * 32;           // 32 x 128

    const int tid = threadIdx.x;
    const int e0 = blockIdx.x * 64;

    // stage f_edges tile + W_edge
    for (int i = tid; i < 512; i += 256)
        ((float4*)sh_fe)[i] = ((const float4*)(f_edges + (size_t)e0 * 32))[i];
    for (int i = tid; i < 1024; i += 256)
        ((float4*)sh_we)[i] = ((const float4*)W_edge)[i];
    __syncthreads();

    // n_input tile: each warp owns rows {w, w+8, ..., w+56}, lane = column group
    {
        const int r0 = tid >> 5;   // warp id
        const int c  = tid & 31;
        float accv[8][4];
#pragma unroll
        for (int ri = 0; ri < 8; ri++)
#pragma unroll
            for (int j = 0; j < 4; j++) accv[ri][j] = 0.f;
#pragma unroll
        for (int k = 0; k < 32; k++) {
            float wv[4];
#pragma unroll
            for (int j = 0; j < 4; j++) wv[j] = sh_we[k * 128 + c + 32 * j];
#pragma unroll
            for (int ri = 0; ri < 8; ri++) {
                float f = sh_fe[(r0 + 8 * ri) * 32 + k];
#pragma unroll
                for (int j = 0; j < 4; j++) accv[ri][j] += f * wv[j];
            }
        }
#pragma unroll
        for (int ri = 0; ri < 8; ri++) {
            int row = r0 + 8 * ri;
            int e = e0 + row;
#pragma unroll
            for (int j = 0; j < 4; j++) {
                float v = (e == 0) ? 0.f : accv[ri][j];
                sh_a[row * A_STRIDE + c + 32 * j] = v;
                msg0[(size_t)e * 128 + c + 32 * j] = v;
            }
        }
    }

    // tf32 GEMM: acc[mt][nt][4]; warps 2m x 4n; warp tile 32m x 96n (gate-aligned)
    const int warp = tid >> 5, lane = tid & 31;
    const int wm = warp >> 2, wn = warp & 3;
    const int g = lane >> 2, t = lane & 3;

    float acc[2][12][4];
#pragma unroll
    for (int a = 0; a < 2; a++)
#pragma unroll
        for (int b = 0; b < 12; b++)
#pragma unroll
            for (int c = 0; c < 4; c++) acc[a][b][c] = 0.f;

    for (int kc = 0; kc < 128; kc += 32) {
        __syncthreads();   // prior reads done (also guards the A-build on first iter)
#pragma unroll
        for (int it = 0; it < 12; it++) {
            int i = tid + it * 256;         // 0..3071
            int j = i >> 3, kg = i & 7;
            *(float4*)(sh_w + j * W_STRIDE + kg * 4) =
                *(const float4*)(W_ih + (size_t)j * 128 + kc + kg * 4);
        }
        __syncthreads();
#pragma unroll
        for (int ks = 0; ks < 4; ks++) {
            uint32_t afr[2][4];
#pragma unroll
            for (int mt = 0; mt < 2; mt++) {
                const float* base = sh_a + (wm * 32 + mt * 16 + g) * A_STRIDE + kc + ks * 8 + t;
                afr[mt][0] = f2t(base[0]);
                afr[mt][1] = f2t(base[8 * A_STRIDE]);
                afr[mt][2] = f2t(base[4]);
                afr[mt][3] = f2t(base[8 * A_STRIDE + 4]);
            }
#pragma unroll
            for (int nt = 0; nt < 12; nt++) {
                int colb = (nt >> 2) * 128 + wn * 32 + (nt & 3) * 8;
                const float* bb = sh_w + (colb + g) * W_STRIDE + ks * 8 + t;
                uint32_t bfr[2] = { f2t(bb[0]), f2t(bb[4]) };
                mma8(acc[0][nt], afr[0], bfr);
                mma8(acc[1][nt], afr[1], bfr);
            }
        }
    }

    // epilogue: gi = acc + b_ih
#pragma unroll
    for (int mt = 0; mt < 2; mt++) {
#pragma unroll
        for (int i = 0; i < 2; i++) {
            int row = wm * 32 + mt * 16 + i * 8 + g;
            size_t gb = (size_t)(e0 + row) * 384;
#pragma unroll
            for (int gate = 0; gate < 3; gate++) {
#pragma unroll
                for (int q = 0; q < 4; q++) {
                    int col = gate * 128 + wn * 32 + q * 8 + 2 * t;
                    float2 bi = *(const float2*)(b_ih + col);
                    float2 o;
                    o.x = acc[mt][gate * 4 + q][2 * i] + bi.x;
                    o.y = acc[mt][gate * 4 + q][2 * i + 1] + bi.y;
                    *(float2*)(gi + gb + col) = o;
                }
            }
        }
    }
}

// ======================================================================
// k_agg: a_message[n] = sum_{k<6} message[node2edge[n][k]]
// ======================================================================
__global__ __launch_bounds__(256) void k_agg(
    const float* __restrict__ msg, const int* __restrict__ n2e,
    float* __restrict__ amsg)
{
    int gid = blockIdx.x * 256 + threadIdx.x;
    int node = gid >> 5, lane = gid & 31;
    const int* ne = n2e + node * 6;
    float4 acc = {0.f, 0.f, 0.f, 0.f};
#pragma unroll
    for (int k = 0; k < 6; k++) {
        int e = __ldg(ne + k);
        float4 v = ((const float4*)(msg + (size_t)e * 128))[lane];
        acc.x += v.x; acc.y += v.y; acc.z += v.z; acc.w += v.w;
    }
    ((float4*)(amsg + (size_t)node * 128))[lane] = acc;
}

// ======================================================================
// k_step: h = amsg[edge2node[e]] - msg_in[b2revb[e]];
//         gh = h @ W_hh^T + b_hh (tf32 GEMM);  GRU update; write msg_out (row 0 masked)
// ======================================================================
__global__ __launch_bounds__(256) void k_step(
    const float* __restrict__ amsg, const float* __restrict__ msg_in,
    const int* __restrict__ edge2node, const int* __restrict__ b2revb,
    const float* __restrict__ W_hh, const float* __restrict__ b_hh,
    const float* __restrict__ gi, float* __restrict__ msg_out)
{
    extern __shared__ float smem[];
    float* sh_a = smem;                   // 64 x A_STRIDE (h tile, fp32)
    float* sh_w = smem + 64 * A_STRIDE;   // 384 x W_STRIDE

    const int tid = threadIdx.x;
    const int e0 = blockIdx.x * 64;

    // gather/build h tile
    {
        int row = tid >> 2, part = tid & 3;
        int e = e0 + row;
        int sn = __ldg(edge2node + e);
        int sr = __ldg(b2revb + e);
        const float4* pa = (const float4*)(amsg + (size_t)sn * 128);
        const float4* pb = (const float4*)(msg_in + (size_t)sr * 128);
#pragma unroll
        for (int c = 0; c < 8; c++) {
            int c4 = part * 8 + c;        // float4 index 0..31
            float4 va = pa[c4], vb = pb[c4];
            float4 h;
            h.x = va.x - vb.x; h.y = va.y - vb.y;
            h.z = va.z - vb.z; h.w = va.w - vb.w;
            *(float4*)(sh_a + row * A_STRIDE + c4 * 4) = h;
        }
    }

    const int warp = tid >> 5, lane = tid & 31;
    const int wm = warp >> 2, wn = warp & 3;
    const int g = lane >> 2, t = lane & 3;

    float acc[2][12][4];
#pragma unroll
    for (int a = 0; a < 2; a++)
#pragma unroll
        for (int b = 0; b < 12; b++)
#pragma unroll
            for (int c = 0; c < 4; c++) acc[a][b][c] = 0.f;

    for (int kc = 0; kc < 128; kc += 32) {
        __syncthreads();
#pragma unroll
        for (int it = 0; it < 12; it++) {
            int i = tid + it * 256;
            int j = i >> 3, kg = i & 7;
            *(float4*)(sh_w + j * W_STRIDE + kg * 4) =
                *(const float4*)(W_hh + (size_t)j * 128 + kc + kg * 4);
        }
        __syncthreads();
#pragma unroll
        for (int ks = 0; ks < 4; ks++) {
            uint32_t afr[2][4];
#pragma unroll
            for (int mt = 0; mt < 2; mt++) {
                const float* base = sh_a + (wm * 32 + mt * 16 + g) * A_STRIDE + kc + ks * 8 + t;
                afr[mt][0] = f2t(base[0]);
                afr[mt][1] = f2t(base[8 * A_STRIDE]);
                afr[mt][2] = f2t(base[4]);
                afr[mt][3] = f2t(base[8 * A_STRIDE + 4]);
            }
#pragma unroll
            for (int nt = 0; nt < 12; nt++) {
                int colb = (nt >> 2) * 128 + wn * 32 + (nt & 3) * 8;
                const float* bb = sh_w + (colb + g) * W_STRIDE + ks * 8 + t;
                uint32_t bfr[2] = { f2t(bb[0]), f2t(bb[4]) };
                mma8(acc[0][nt], afr[0], bfr);
                mma8(acc[1][nt], afr[1], bfr);
            }
        }
    }

    // hoist b_hh (depends only on q,t)
    float2 bhr[4], bhz[4], bhn[4];
#pragma unroll
    for (int q = 0; q < 4; q++) {
        int j = wn * 32 + q * 8 + 2 * t;
        bhr[q] = *(const float2*)(b_hh + j);
        bhz[q] = *(const float2*)(b_hh + 128 + j);
        bhn[q] = *(const float2*)(b_hh + 256 + j);
    }

    // GRU epilogue
#pragma unroll
    for (int mt = 0; mt < 2; mt++) {
#pragma unroll
        for (int i = 0; i < 2; i++) {
            int row = wm * 32 + mt * 16 + i * 8 + g;
            int e = e0 + row;
            size_t gb = (size_t)e * 384;
#pragma unroll
            for (int q = 0; q < 4; q++) {
                int j = wn * 32 + q * 8 + 2 * t;
                float2 gir = *(const float2*)(gi + gb + j);
                float2 giz = *(const float2*)(gi + gb + 128 + j);
                float2 gin = *(const float2*)(gi + gb + 256 + j);
                float ghr0 = acc[mt][q][2 * i]     + bhr[q].x;
                float ghr1 = acc[mt][q][2 * i + 1] + bhr[q].y;
                float ghz0 = acc[mt][4 + q][2 * i]     + bhz[q].x;
                float ghz1 = acc[mt][4 + q][2 * i + 1] + bhz[q].y;
                float ghn0 = acc[mt][8 + q][2 * i]     + bhn[q].x;
                float ghn1 = acc[mt][8 + q][2 * i + 1] + bhn[q].y;
                float r0 = sigm(gir.x + ghr0), r1 = sigm(gir.y + ghr1);
                float z0 = sigm(giz.x + ghz0), z1 = sigm(giz.y + ghz1);
                float n0 = tanhf(gin.x + r0 * ghn0), n1 = tanhf(gin.y + r1 * ghn1);
                float2 hh = *(const float2*)(sh_a + row * A_STRIDE + j);
                float o0 = (1.f - z0) * n0 + z0 * hh.x;
                float o1 = (1.f - z1) * n1 + z1 * hh.y;
                if (e == 0) { o0 = 0.f; o1 = 0.f; }
                float2 o; o.x = o0; o.y = o1;
                *(float2*)(msg_out + (size_t)e * 128 + j) = o;
            }
        }
    }
}

// ======================================================================
// k_readout: out = relu([emb[f_nodes], amsg] @ W_ro + b_ro)   (BM=64, BN=256, K=256)
// ======================================================================
__global__ __launch_bounds__(256) void k_readout(
    const int* __restrict__ f_nodes, const float* __restrict__ emb,
    const float* __restrict__ amsg, const float* __restrict__ W_ro,
    const float* __restrict__ b_ro, float* __restrict__ out)
{
    extern __shared__ float smem[];
    float* sh_a = smem;                      // 64 x RO_A_STRIDE
    float* sh_w = smem + 64 * RO_A_STRIDE;   // 32 x RO_W_STRIDE, [k][n]

    const int tid = threadIdx.x;
    const int n0 = blockIdx.x * 64;

    // build A tile rows = [emb[f_nodes[n]] | amsg[n]]
    {
        int row = tid >> 2, part = tid & 3;
        int n = n0 + row;
        bool valid = n < NN;
        int nc = valid ? n : (NN - 1);
        int tok = __ldg(f_nodes + nc);
        const float4* pe = (const float4*)(emb + (size_t)tok * 128);
        const float4* pm = (const float4*)(amsg + (size_t)nc * 128);
#pragma unroll
        for (int c = 0; c < 16; c++) {
            int c4 = part * 16 + c;          // 0..63 float4s = 256 floats
            float4 v;
            if (!valid) { v.x = v.y = v.z = v.w = 0.f; }
            else if (c4 < 32) v = pe[c4];
            else v = pm[c4 - 32];
            *(float4*)(sh_a + row * RO_A_STRIDE + c4 * 4) = v;
        }
    }

    const int warp = tid >> 5, lane = tid & 31;
    const int wm = warp >> 2, wn = warp & 3;
    const int g = lane >> 2, t = lane & 3;

    float acc[2][8][4];
#pragma unroll
    for (int a = 0; a < 2; a++)
#pragma unroll
        for (int b = 0; b < 8; b++)
#pragma unroll
            for (int c = 0; c < 4; c++) acc[a][b][c] = 0.f;

    for (int kc = 0; kc < 256; kc += 32) {
        __syncthreads();
#pragma unroll
        for (int it = 0; it < 8; it++) {
            int i = tid + it * 256;           // 0..2047 float4 ids
            int kk = i >> 6, n4 = i & 63;
            *(float4*)(sh_w + kk * RO_W_STRIDE + n4 * 4) =
                *(const float4*)(W_ro + (size_t)(kc + kk) * 256 + n4 * 4);
        }
        __syncthreads();
#pragma unroll
        for (int ks = 0; ks < 4; ks++) {
            uint32_t afr[2][4];
#pragma unroll
            for (int mt = 0; mt < 2; mt++) {
                const float* base = sh_a + (wm * 32 + mt * 16 + g) * RO_A_STRIDE + kc + ks * 8 + t;
                afr[mt][0] = f2t(base[0]);
                afr[mt][1] = f2t(base[8 * RO_A_STRIDE]);
                afr[mt][2] = f2t(base[4]);
                afr[mt][3] = f2t(base[8 * RO_A_STRIDE + 4]);
            }
#pragma unroll
            for (int nt = 0; nt < 8; nt++) {
                int colb = wn * 64 + nt * 8;
                const float* bb = sh_w + (ks * 8 + t) * RO_W_STRIDE + colb + g;
                uint32_t bfr[2] = { f2t(bb[0]), f2t(bb[4 * RO_W_STRIDE]) };
                mma8(acc[0][nt], afr[0], bfr);
                mma8(acc[1][nt], afr[1], bfr);
            }
        }
    }

    // epilogue: relu(acc + b_ro)
#pragma unroll
    for (int mt = 0; mt < 2; mt++) {
#pragma unroll
        for (int i = 0; i < 2; i++) {
            int row = wm * 32 + mt * 16 + i * 8 + g;
            int n = n0 + row;
            if (n >= NN) continue;
#pragma unroll
            for (int nt = 0; nt < 8; nt++) {
                int col = wn * 64 + nt * 8 + 2 * t;
                float2 br = *(const float2*)(b_ro + col);
                float2 o;
                o.x = fmaxf(acc[mt][nt][2 * i] + br.x, 0.f);
                o.y = fmaxf(acc[mt][nt][2 * i + 1] + br.y, 0.f);
                *(float2*)(out + (size_t)n * 256 + col) = o;
            }
        }
    }
}

// ======================================================================
extern "C" void kernel_launch(void* const* d_in, const int* in_sizes, int n_in,
                              void* d_out, int out_size)
{
    const int*   f_nodes   = (const int*)d_in[0];
    const float* f_edges   = (const float*)d_in[1];
    const int*   node2edge = (const int*)d_in[2];
    const int*   edge2node = (const int*)d_in[3];
    const int*   b2revb    = (const int*)d_in[4];
    const float* emb       = (const float*)d_in[5];
    const float* W_edge    = (const float*)d_in[6];
    const float* W_ih      = (const float*)d_in[7];
    const float* W_hh      = (const float*)d_in[8];
    const float* b_ih      = (const float*)d_in[9];
    const float* b_hh      = (const float*)d_in[10];
    const float* W_ro      = (const float*)d_in[11];
    const float* b_ro      = (const float*)d_in[12];
    float* outp = (float*)d_out;

    float *msgA, *msgB, *giP, *amsgP;
    cudaGetSymbolAddress((void**)&msgA, g_msgA);
    cudaGetSymbolAddress((void**)&msgB, g_msgB);
    cudaGetSymbolAddress((void**)&giP, g_gi);
    cudaGetSymbolAddress((void**)&amsgP, g_amsg);

    const int smem_main = SMEM_MAIN_FLOATS * 4;   // 89088 B
    const int smem_ro   = SMEM_RO_FLOATS * 4;     // 100352 B
    cudaFuncSetAttribute(k_init,    cudaFuncAttributeMaxDynamicSharedMemorySize, smem_main);
    cudaFuncSetAttribute(k_step,    cudaFuncAttributeMaxDynamicSharedMemorySize, smem_main);
    cudaFuncSetAttribute(k_readout, cudaFuncAttributeMaxDynamicSharedMemorySize, smem_ro);

    k_init<<<EE / 64, 256, smem_main>>>(f_edges, W_edge, W_ih, b_ih, msgA, giP);

    float* cur = msgA;
    float* nxt = msgB;
    for (int s = 0; s < 4; s++) {
        k_agg<<<(NN * 32) / 256, 256>>>(cur, node2edge, amsgP);
        k_step<<<EE / 64, 256, smem_main>>>(amsgP, cur, edge2node, b2revb,
                                            W_hh, b_hh, giP, nxt);
        float* tmp = cur; cur = nxt; nxt = tmp;
    }
    k_agg<<<(NN * 32) / 256, 256>>>(cur, node2edge, amsgP);
    k_readout<<<(NN + 63) / 64, 256, smem_ro>>>(f_nodes, emb, amsgP, W_ro, b_ro, outp);
}

// round 2
// speedup vs baseline: 1.0627x; 1.0627x over previous
#include <cuda_runtime.h>
#include <cstdint>

#define NN 100000
#define EE 400000
#define DD 128

// ---------------- scratch (static device arrays; no cudaMalloc) ----------------
__device__ float g_msgA[(size_t)EE * DD];        // 204.8 MB
__device__ float g_msgB[(size_t)EE * DD];        // 204.8 MB
__device__ float g_gi[(size_t)EE * 3 * DD];      // 614.4 MB
__device__ float g_amsg[(size_t)NN * DD];        // 51.2 MB

// ---------------- helpers ----------------
__device__ __forceinline__ uint32_t f2t(float x) {
    uint32_t r;
    asm("cvt.rna.tf32.f32 %0, %1;" : "=r"(r) : "f"(x));
    return r;
}

__device__ __forceinline__ void mma8(float* d, const uint32_t* a, const uint32_t* b) {
    asm volatile(
        "mma.sync.aligned.m16n8k8.row.col.f32.tf32.tf32.f32 "
        "{%0,%1,%2,%3}, {%4,%5,%6,%7}, {%8,%9}, {%0,%1,%2,%3};"
        : "+f"(d[0]), "+f"(d[1]), "+f"(d[2]), "+f"(d[3])
        : "r"(a[0]), "r"(a[1]), "r"(a[2]), "r"(a[3]), "r"(b[0]), "r"(b[1]));
}

__device__ __forceinline__ float fast_tanh(float x) {
    float r;
    asm("tanh.approx.f32 %0, %1;" : "=f"(r) : "f"(x));
    return r;
}
__device__ __forceinline__ float sigm(float x) {
    return 0.5f * fast_tanh(0.5f * x) + 0.5f;
}

// Shared-memory layout constants
#define A_STRIDE 132           // 128 + 4 pad (A tile, fp32, conflict-free frag loads)
#define W_STRIDE 40            // paired-tf32 W layout: 32 k-values as 16 (k,k+4) pairs + pad
#define SMEM_MAIN_FLOATS (64 * A_STRIDE + 384 * W_STRIDE)    // 8448 + 15360 = 23808
#define RO_A_STRIDE 260        // 256 + 4
#define RO_W_STRIDE 520        // pair-row layout: 512 + 8 pad
#define SMEM_RO_FLOATS (64 * RO_A_STRIDE + 16 * RO_W_STRIDE) // 16640 + 8320 = 24960

// no-op kernel: shifts launch index so ncu (-s 5 -c 1) profiles k_step
__global__ void k_nop() {}

// ======================================================================
// W chunk loader: convert to tf32 and store (k, k+4) pairs adjacently.
// Layout: sh_w[j*W_STRIDE + grp*8 + c*2 + {0,1}] = tf32(W[j][kc+grp*8+c (+4)])
// ======================================================================
__device__ __forceinline__ void load_w_chunk(uint32_t* sh_w, const float* __restrict__ W,
                                             int kc, int tid) {
#pragma unroll
    for (int it = 0; it < 6; it++) {
        int i = tid + it * 256;           // 0..1535  (384 rows x 4 groups)
        int j = i >> 2, grp = i & 3;
        const float* src = W + (size_t)j * 128 + kc + grp * 8;
        float4 lo = *(const float4*)(src);
        float4 hi = *(const float4*)(src + 4);
        uint32_t* dst = sh_w + j * W_STRIDE + grp * 8;
        dst[0] = f2t(lo.x); dst[1] = f2t(hi.x);
        dst[2] = f2t(lo.y); dst[3] = f2t(hi.y);
        dst[4] = f2t(lo.z); dst[5] = f2t(hi.z);
        dst[6] = f2t(lo.w); dst[7] = f2t(hi.w);
    }
}

// ======================================================================
// k_init: n_input = f_edges @ W_edge (fp32, K=32) -> write msg0 (+zero row 0),
//         then gi = n_input @ W_ih^T + b_ih  (tf32 GEMM, BM=64, BN=384, K=128)
// ======================================================================
__global__ __launch_bounds__(256) void k_init(
    const float* __restrict__ f_edges, const float* __restrict__ W_edge,
    const float* __restrict__ W_ih, const float* __restrict__ b_ih,
    float* __restrict__ msg0, float* __restrict__ gi)
{
    extern __shared__ float smem[];
    float* sh_a = smem;                          // 64 x A_STRIDE (n_input tile, fp32)
    uint32_t* sh_w = (uint32_t*)(smem + 64 * A_STRIDE);  // 384 x W_STRIDE (tf32 pairs)
    float* sh_fe = (float*)sh_w;                 // 64 x 32   (overlaps W region)
    float* sh_we = sh_fe + 64 * 32;              // 32 x 128

    const int tid = threadIdx.x;
    const int e0 = blockIdx.x * 64;

    // stage f_edges tile + W_edge
    for (int i = tid; i < 512; i += 256)
        ((float4*)sh_fe)[i] = ((const float4*)(f_edges + (size_t)e0 * 32))[i];
    for (int i = tid; i < 1024; i += 256)
        ((float4*)sh_we)[i] = ((const float4*)W_edge)[i];
    __syncthreads();

    // n_input tile: each warp owns rows {w, w+8, ..., w+56}, lane = column group
    {
        const int r0 = tid >> 5;
        const int c  = tid & 31;
        float accv[8][4];
#pragma unroll
        for (int ri = 0; ri < 8; ri++)
#pragma unroll
            for (int j = 0; j < 4; j++) accv[ri][j] = 0.f;
#pragma unroll
        for (int k = 0; k < 32; k++) {
            float wv[4];
#pragma unroll
            for (int j = 0; j < 4; j++) wv[j] = sh_we[k * 128 + c + 32 * j];
#pragma unroll
            for (int ri = 0; ri < 8; ri++) {
                float f = sh_fe[(r0 + 8 * ri) * 32 + k];
#pragma unroll
                for (int j = 0; j < 4; j++) accv[ri][j] += f * wv[j];
            }
        }
#pragma unroll
        for (int ri = 0; ri < 8; ri++) {
            int row = r0 + 8 * ri;
            int e = e0 + row;
#pragma unroll
            for (int j = 0; j < 4; j++) {
                float v = (e == 0) ? 0.f : accv[ri][j];
                sh_a[row * A_STRIDE + c + 32 * j] = v;
                msg0[(size_t)e * 128 + c + 32 * j] = v;
            }
        }
    }

    const int warp = tid >> 5, lane = tid & 31;
    const int wm = warp >> 2, wn = warp & 3;
    const int g = lane >> 2, t = lane & 3;

    float acc[2][12][4];
#pragma unroll
    for (int a = 0; a < 2; a++)
#pragma unroll
        for (int b = 0; b < 12; b++)
#pragma unroll
            for (int c = 0; c < 4; c++) acc[a][b][c] = 0.f;

    for (int kc = 0; kc < 128; kc += 32) {
        __syncthreads();   // prior reads done (also guards the A-build on first iter)
        load_w_chunk(sh_w, W_ih, kc, tid);
        __syncthreads();
#pragma unroll
        for (int ks = 0; ks < 4; ks++) {
            uint32_t afr[2][4];
#pragma unroll
            for (int mt = 0; mt < 2; mt++) {
                const float* base = sh_a + (wm * 32 + mt * 16 + g) * A_STRIDE + kc + ks * 8 + t;
                afr[mt][0] = f2t(base[0]);
                afr[mt][1] = f2t(base[8 * A_STRIDE]);
                afr[mt][2] = f2t(base[4]);
                afr[mt][3] = f2t(base[8 * A_STRIDE + 4]);
            }
#pragma unroll
            for (int nt = 0; nt < 12; nt++) {
                int colb = (nt >> 2) * 128 + wn * 32 + (nt & 3) * 8;
                uint2 b2 = *(const uint2*)(sh_w + (colb + g) * W_STRIDE + ks * 8 + t * 2);
                mma8(acc[0][nt], afr[0], (const uint32_t*)&b2);
                mma8(acc[1][nt], afr[1], (const uint32_t*)&b2);
            }
        }
    }

    // epilogue: gi = acc + b_ih
#pragma unroll
    for (int mt = 0; mt < 2; mt++) {
#pragma unroll
        for (int i = 0; i < 2; i++) {
            int row = wm * 32 + mt * 16 + i * 8 + g;
            size_t gb = (size_t)(e0 + row) * 384;
#pragma unroll
            for (int gate = 0; gate < 3; gate++) {
#pragma unroll
                for (int q = 0; q < 4; q++) {
                    int col = gate * 128 + wn * 32 + q * 8 + 2 * t;
                    float2 bi = *(const float2*)(b_ih + col);
                    float2 o;
                    o.x = acc[mt][gate * 4 + q][2 * i] + bi.x;
                    o.y = acc[mt][gate * 4 + q][2 * i + 1] + bi.y;
                    *(float2*)(gi + gb + col) = o;
                }
            }
        }
    }
}

// ======================================================================
// k_agg: a_message[n] = sum_{k<6} message[node2edge[n][k]]
// ======================================================================
__global__ __launch_bounds__(256) void k_agg(
    const float* __restrict__ msg, const int* __restrict__ n2e,
    float* __restrict__ amsg)
{
    int gid = blockIdx.x * 256 + threadIdx.x;
    int node = gid >> 5, lane = gid & 31;
    const int* ne = n2e + node * 6;
    float4 acc = {0.f, 0.f, 0.f, 0.f};
#pragma unroll
    for (int k = 0; k < 6; k++) {
        int e = __ldg(ne + k);
        float4 v = ((const float4*)(msg + (size_t)e * 128))[lane];
        acc.x += v.x; acc.y += v.y; acc.z += v.z; acc.w += v.w;
    }
    ((float4*)(amsg + (size_t)node * 128))[lane] = acc;
}

// ======================================================================
// k_step: h = amsg[edge2node[e]] - msg_in[b2revb[e]];
//         gh = h @ W_hh^T + b_hh (tf32 GEMM);  GRU update; write msg_out (row 0 masked)
// ======================================================================
__global__ __launch_bounds__(256) void k_step(
    const float* __restrict__ amsg, const float* __restrict__ msg_in,
    const int* __restrict__ edge2node, const int* __restrict__ b2revb,
    const float* __restrict__ W_hh, const float* __restrict__ b_hh,
    const float* __restrict__ gi, float* __restrict__ msg_out)
{
    extern __shared__ float smem[];
    float* sh_a = smem;                                  // 64 x A_STRIDE (h tile, fp32)
    uint32_t* sh_w = (uint32_t*)(smem + 64 * A_STRIDE);  // 384 x W_STRIDE (tf32 pairs)

    const int tid = threadIdx.x;
    const int e0 = blockIdx.x * 64;

    // gather/build h tile
    {
        int row = tid >> 2, part = tid & 3;
        int e = e0 + row;
        int sn = __ldg(edge2node + e);
        int sr = __ldg(b2revb + e);
        const float4* pa = (const float4*)(amsg + (size_t)sn * 128);
        const float4* pb = (const float4*)(msg_in + (size_t)sr * 128);
#pragma unroll
        for (int c = 0; c < 8; c++) {
            int c4 = part * 8 + c;
            float4 va = pa[c4], vb = pb[c4];
            float4 h;
            h.x = va.x - vb.x; h.y = va.y - vb.y;
            h.z = va.z - vb.z; h.w = va.w - vb.w;
            *(float4*)(sh_a + row * A_STRIDE + c4 * 4) = h;
        }
    }

    const int warp = tid >> 5, lane = tid & 31;
    const int wm = warp >> 2, wn = warp & 3;
    const int g = lane >> 2, t = lane & 3;

    float acc[2][12][4];
#pragma unroll
    for (int a = 0; a < 2; a++)
#pragma unroll
        for (int b = 0; b < 12; b++)
#pragma unroll
            for (int c = 0; c < 4; c++) acc[a][b][c] = 0.f;

    for (int kc = 0; kc < 128; kc += 32) {
        __syncthreads();
        load_w_chunk(sh_w, W_hh, kc, tid);
        __syncthreads();
#pragma unroll
        for (int ks = 0; ks < 4; ks++) {
            uint32_t afr[2][4];
#pragma unroll
            for (int mt = 0; mt < 2; mt++) {
                const float* base = sh_a + (wm * 32 + mt * 16 + g) * A_STRIDE + kc + ks * 8 + t;
                afr[mt][0] = f2t(base[0]);
                afr[mt][1] = f2t(base[8 * A_STRIDE]);
                afr[mt][2] = f2t(base[4]);
                afr[mt][3] = f2t(base[8 * A_STRIDE + 4]);
            }
#pragma unroll
            for (int nt = 0; nt < 12; nt++) {
                int colb = (nt >> 2) * 128 + wn * 32 + (nt & 3) * 8;
                uint2 b2 = *(const uint2*)(sh_w + (colb + g) * W_STRIDE + ks * 8 + t * 2);
                mma8(acc[0][nt], afr[0], (const uint32_t*)&b2);
                mma8(acc[1][nt], afr[1], (const uint32_t*)&b2);
            }
        }
    }

    // hoist b_hh (depends only on q,t)
    float2 bhr[4], bhz[4], bhn[4];
#pragma unroll
    for (int q = 0; q < 4; q++) {
        int j = wn * 32 + q * 8 + 2 * t;
        bhr[q] = *(const float2*)(b_hh + j);
        bhz[q] = *(const float2*)(b_hh + 128 + j);
        bhn[q] = *(const float2*)(b_hh + 256 + j);
    }

    // GRU epilogue (tanh.approx-based nonlinearities)
#pragma unroll
    for (int mt = 0; mt < 2; mt++) {
#pragma unroll
        for (int i = 0; i < 2; i++) {
            int row = wm * 32 + mt * 16 + i * 8 + g;
            int e = e0 + row;
            size_t gb = (size_t)e * 384;
#pragma unroll
            for (int q = 0; q < 4; q++) {
                int j = wn * 32 + q * 8 + 2 * t;
                float2 gir = *(const float2*)(gi + gb + j);
                float2 giz = *(const float2*)(gi + gb + 128 + j);
                float2 gin = *(const float2*)(gi + gb + 256 + j);
                float ghr0 = acc[mt][q][2 * i]     + bhr[q].x;
                float ghr1 = acc[mt][q][2 * i + 1] + bhr[q].y;
                float ghz0 = acc[mt][4 + q][2 * i]     + bhz[q].x;
                float ghz1 = acc[mt][4 + q][2 * i + 1] + bhz[q].y;
                float ghn0 = acc[mt][8 + q][2 * i]     + bhn[q].x;
                float ghn1 = acc[mt][8 + q][2 * i + 1] + bhn[q].y;
                float r0 = sigm(gir.x + ghr0), r1 = sigm(gir.y + ghr1);
                float z0 = sigm(giz.x + ghz0), z1 = sigm(giz.y + ghz1);
                float n0 = fast_tanh(gin.x + r0 * ghn0), n1 = fast_tanh(gin.y + r1 * ghn1);
                float2 hh = *(const float2*)(sh_a + row * A_STRIDE + j);
                float o0 = (1.f - z0) * n0 + z0 * hh.x;
                float o1 = (1.f - z1) * n1 + z1 * hh.y;
                if (e == 0) { o0 = 0.f; o1 = 0.f; }
                float2 o; o.x = o0; o.y = o1;
                *(float2*)(msg_out + (size_t)e * 128 + j) = o;
            }
        }
    }
}

// ======================================================================
// k_readout: out = relu([emb[f_nodes], amsg] @ W_ro + b_ro)   (BM=64, BN=256, K=256)
// W_ro staged in smem as tf32 pair-rows: sh_w[(ks*4+t)*RO_W_STRIDE + n*2 + {0,1}]
//   = tf32(W_ro[kc+ks*8+t][n]), tf32(W_ro[kc+ks*8+t+4][n])
// ======================================================================
__global__ __launch_bounds__(256) void k_readout(
    const int* __restrict__ f_nodes, const float* __restrict__ emb,
    const float* __restrict__ amsg, const float* __restrict__ W_ro,
    const float* __restrict__ b_ro, float* __restrict__ out)
{
    extern __shared__ float smem[];
    float* sh_a = smem;                                     // 64 x RO_A_STRIDE
    uint32_t* sh_w = (uint32_t*)(smem + 64 * RO_A_STRIDE);  // 16 x RO_W_STRIDE

    const int tid = threadIdx.x;
    const int n0 = blockIdx.x * 64;

    // build A tile rows = [emb[f_nodes[n]] | amsg[n]]
    {
        int row = tid >> 2, part = tid & 3;
        int n = n0 + row;
        bool valid = n < NN;
        int nc = valid ? n : (NN - 1);
        int tok = __ldg(f_nodes + nc);
        const float4* pe = (const float4*)(emb + (size_t)tok * 128);
        const float4* pm = (const float4*)(amsg + (size_t)nc * 128);
#pragma unroll
        for (int c = 0; c < 16; c++) {
            int c4 = part * 16 + c;
            float4 v;
            if (!valid) { v.x = v.y = v.z = v.w = 0.f; }
            else if (c4 < 32) v = pe[c4];
            else v = pm[c4 - 32];
            *(float4*)(sh_a + row * RO_A_STRIDE + c4 * 4) = v;
        }
    }

    const int warp = tid >> 5, lane = tid & 31;
    const int wm = warp >> 2, wn = warp & 3;
    const int g = lane >> 2, t = lane & 3;

    float acc[2][8][4];
#pragma unroll
    for (int a = 0; a < 2; a++)
#pragma unroll
        for (int b = 0; b < 8; b++)
#pragma unroll
            for (int c = 0; c < 4; c++) acc[a][b][c] = 0.f;

    for (int kc = 0; kc < 256; kc += 32) {
        __syncthreads();
#pragma unroll
        for (int it = 0; it < 4; it++) {
            int i = tid + it * 256;        // 0..1023  (16 p-rows x 64 float4-cols)
            int p = i >> 6, n4 = i & 63;
            int ks = p >> 2, tt = p & 3;
            const float* srcL = W_ro + (size_t)(kc + ks * 8 + tt) * 256 + n4 * 4;
            const float* srcH = W_ro + (size_t)(kc + ks * 8 + tt + 4) * 256 + n4 * 4;
            float4 lo = *(const float4*)srcL;
            float4 hi = *(const float4*)srcH;
            uint32_t* dst = sh_w + p * RO_W_STRIDE + n4 * 8;
            dst[0] = f2t(lo.x); dst[1] = f2t(hi.x);
            dst[2] = f2t(lo.y); dst[3] = f2t(hi.y);
            dst[4] = f2t(lo.z); dst[5] = f2t(hi.z);
            dst[6] = f2t(lo.w); dst[7] = f2t(hi.w);
        }
        __syncthreads();
#pragma unroll
        for (int ks = 0; ks < 4; ks++) {
            uint32_t afr[2][4];
#pragma unroll
            for (int mt = 0; mt < 2; mt++) {
                const float* base = sh_a + (wm * 32 + mt * 16 + g) * RO_A_STRIDE + kc + ks * 8 + t;
                afr[mt][0] = f2t(base[0]);
                afr[mt][1] = f2t(base[8 * RO_A_STRIDE]);
                afr[mt][2] = f2t(base[4]);
                afr[mt][3] = f2t(base[8 * RO_A_STRIDE + 4]);
            }
#pragma unroll
            for (int nt = 0; nt < 8; nt++) {
                int colb = wn * 64 + nt * 8;
                uint2 b2 = *(const uint2*)(sh_w + (ks * 4 + t) * RO_W_STRIDE + (colb + g) * 2);
                mma8(acc[0][nt], afr[0], (const uint32_t*)&b2);
                mma8(acc[1][nt], afr[1], (const uint32_t*)&b2);
            }
        }
    }

    // epilogue: relu(acc + b_ro)
#pragma unroll
    for (int mt = 0; mt < 2; mt++) {
#pragma unroll
        for (int i = 0; i < 2; i++) {
            int row = wm * 32 + mt * 16 + i * 8 + g;
            int n = n0 + row;
            if (n >= NN) continue;
#pragma unroll
            for (int nt = 0; nt < 8; nt++) {
                int col = wn * 64 + nt * 8 + 2 * t;
                float2 br = *(const float2*)(b_ro + col);
                float2 o;
                o.x = fmaxf(acc[mt][nt][2 * i] + br.x, 0.f);
                o.y = fmaxf(acc[mt][nt][2 * i + 1] + br.y, 0.f);
                *(float2*)(out + (size_t)n * 256 + col) = o;
            }
        }
    }
}

// ======================================================================
extern "C" void kernel_launch(void* const* d_in, const int* in_sizes, int n_in,
                              void* d_out, int out_size)
{
    const int*   f_nodes   = (const int*)d_in[0];
    const float* f_edges   = (const float*)d_in[1];
    const int*   node2edge = (const int*)d_in[2];
    const int*   edge2node = (const int*)d_in[3];
    const int*   b2revb    = (const int*)d_in[4];
    const float* emb       = (const float*)d_in[5];
    const float* W_edge    = (const float*)d_in[6];
    const float* W_ih      = (const float*)d_in[7];
    const float* W_hh      = (const float*)d_in[8];
    const float* b_ih      = (const float*)d_in[9];
    const float* b_hh      = (const float*)d_in[10];
    const float* W_ro      = (const float*)d_in[11];
    const float* b_ro      = (const float*)d_in[12];
    float* outp = (float*)d_out;

    float *msgA, *msgB, *giP, *amsgP;
    cudaGetSymbolAddress((void**)&msgA, g_msgA);
    cudaGetSymbolAddress((void**)&msgB, g_msgB);
    cudaGetSymbolAddress((void**)&giP, g_gi);
    cudaGetSymbolAddress((void**)&amsgP, g_amsg);

    const int smem_main = SMEM_MAIN_FLOATS * 4;   // 95232 B
    const int smem_ro   = SMEM_RO_FLOATS * 4;     // 99840 B
    cudaFuncSetAttribute(k_init,    cudaFuncAttributeMaxDynamicSharedMemorySize, smem_main);
    cudaFuncSetAttribute(k_step,    cudaFuncAttributeMaxDynamicSharedMemorySize, smem_main);
    cudaFuncSetAttribute(k_readout, cudaFuncAttributeMaxDynamicSharedMemorySize, smem_ro);

    k_init<<<EE / 64, 256, smem_main>>>(f_edges, W_edge, W_ih, b_ih, msgA, giP);
    k_nop<<<1, 32>>>();   // shifts ncu -s 5 capture onto k_step

    float* cur = msgA;
    float* nxt = msgB;
    for (int s = 0; s < 4; s++) {
        k_agg<<<(NN * 32) / 256, 256>>>(cur, node2edge, amsgP);
        k_step<<<EE / 64, 256, smem_main>>>(amsgP, cur, edge2node, b2revb,
                                            W_hh, b_hh, giP, nxt);
        float* tmp = cur; cur = nxt; nxt = tmp;
    }
    k_agg<<<(NN * 32) / 256, 256>>>(cur, node2edge, amsgP);
    k_readout<<<(NN + 63) / 64, 256, smem_ro>>>(f_nodes, emb, amsgP, W_ro, b_ro, outp);
}

// round 3
// speedup vs baseline: 1.5392x; 1.4484x over previous
#include <cuda_runtime.h>
#include <cstdint>

#define NN 100000
#define EE 400000
#define NTILES (EE / 64)

// ---------------- scratch (static device arrays; no cudaMalloc) ----------------
__device__ float g_msgA[(size_t)EE * 128];       // 204.8 MB
__device__ float g_msgB[(size_t)EE * 128];       // 204.8 MB
__device__ float g_gi[(size_t)EE * 384];         // 614.4 MB
__device__ float g_amsg[(size_t)NN * 128];       // 51.2 MB

// ---------------- helpers ----------------
__device__ __forceinline__ uint32_t f2t(float x) {
    uint32_t r;
    asm("cvt.rna.tf32.f32 %0, %1;" : "=r"(r) : "f"(x));
    return r;
}

__device__ __forceinline__ void mma8(float* d, const uint32_t* a, const uint32_t* b) {
    asm volatile(
        "mma.sync.aligned.m16n8k8.row.col.f32.tf32.tf32.f32 "
        "{%0,%1,%2,%3}, {%4,%5,%6,%7}, {%8,%9}, {%0,%1,%2,%3};"
        : "+f"(d[0]), "+f"(d[1]), "+f"(d[2]), "+f"(d[3])
        : "r"(a[0]), "r"(a[1]), "r"(a[2]), "r"(a[3]), "r"(b[0]), "r"(b[1]));
}

__device__ __forceinline__ float fast_tanh(float x) {
    float r;
    asm("tanh.approx.f32 %0, %1;" : "=f"(r) : "f"(x));
    return r;
}
__device__ __forceinline__ float sigm(float x) {
    return 0.5f * fast_tanh(0.5f * x) + 0.5f;
}

// W smem swizzle: row p = ks8*4 + t (64 rows), pair (k=ks8*8+t, k+4) for column n
// stored at word offset p*768 + 2*(n ^ xsw(p)). Conflict-free for frag LDS.64
// (lanes g,t) and for the staging STS.64 (lanes ks8).
__device__ __forceinline__ int xsw(int p) {
    return ((p >> 2) & 3) ^ ((((p & 3) ^ (p >> 4)) & 3) << 2);
}

#define A_STRIDE 132                       // words; 4g+t banks -> conflict-free LDS.32
#define A_WORDS  (64 * A_STRIDE)           // 8448
#define W_WORDS  (64 * 768)                // 49152
#define SMEM_BIG ((A_WORDS + W_WORDS) * 4) // 230400 B <= 227KB limit
#define RO_A_STRIDE 260
#define RO_W_STRIDE 520
#define SMEM_RO ((64 * RO_A_STRIDE + 16 * RO_W_STRIDE) * 4)   // 99840 B

// no-op kernel: shifts launch index so ncu (-s 5 -c 1) profiles k_step
__global__ void k_nop() {}

// Load & convert entire W [384 x 128] into swizzled tf32 smem. 512 threads.
__device__ __forceinline__ void load_w_full(uint32_t* sh_w, const float* __restrict__ W,
                                            int tid) {
#pragma unroll
    for (int it = 0; it < 12; it++) {
        int i = tid + it * 512;            // 0..6143 : (j, ks8)
        int j = i >> 4, ks8 = i & 15;
        const float* src = W + (size_t)j * 128 + ks8 * 8;
        float4 lo = *(const float4*)src;
        float4 hi = *(const float4*)(src + 4);
        int pb = ks8 * 4;
        uint2 v;
        v.x = f2t(lo.x); v.y = f2t(hi.x);
        *(uint2*)(sh_w + (pb + 0) * 768 + 2 * (j ^ xsw(pb + 0))) = v;
        v.x = f2t(lo.y); v.y = f2t(hi.y);
        *(uint2*)(sh_w + (pb + 1) * 768 + 2 * (j ^ xsw(pb + 1))) = v;
        v.x = f2t(lo.z); v.y = f2t(hi.z);
        *(uint2*)(sh_w + (pb + 2) * 768 + 2 * (j ^ xsw(pb + 2))) = v;
        v.x = f2t(lo.w); v.y = f2t(hi.w);
        *(uint2*)(sh_w + (pb + 3) * 768 + 2 * (j ^ xsw(pb + 3))) = v;
    }
}

// The shared 64x384 tf32 GEMM mainloop: A (tf32 bits) in sh_a, W swizzled in sh_w.
// Warp grid 2m x 8n; per warp 32 rows x (16 cols per gate). acc[mt][gate*2+q][4].
#define GEMM_MAINLOOP(acc, sh_a, sh_w, wm, wn, g, t)                               \
    _Pragma("unroll")                                                              \
    for (int ks8 = 0; ks8 < 16; ks8++) {                                           \
        uint32_t afr[2][4];                                                        \
        const uint32_t* ab = (sh_a) + ((wm) * 32 + (g)) * A_STRIDE + ks8 * 8 + (t);\
        afr[0][0] = ab[0];              afr[0][1] = ab[8 * A_STRIDE];              \
        afr[0][2] = ab[4];              afr[0][3] = ab[8 * A_STRIDE + 4];          \
        afr[1][0] = ab[16 * A_STRIDE];  afr[1][1] = ab[24 * A_STRIDE];             \
        afr[1][2] = ab[16 * A_STRIDE + 4]; afr[1][3] = ab[24 * A_STRIDE + 4];      \
        int p = ks8 * 4 + (t);                                                     \
        int xs = xsw(p);                                                           \
        const uint32_t* wb = (sh_w) + p * 768;                                     \
        _Pragma("unroll")                                                          \
        for (int nt = 0; nt < 6; nt++) {                                           \
            int colb = (nt >> 1) * 128 + (wn) * 16 + (nt & 1) * 8;                 \
            uint2 b2 = *(const uint2*)(wb + 2 * ((colb + (g)) ^ xs));              \
            mma8(acc[0][nt], afr[0], (const uint32_t*)&b2);                        \
            mma8(acc[1][nt], afr[1], (const uint32_t*)&b2);                        \
        }                                                                          \
    }

// ======================================================================
// k_init (persistent): n_input = f_edges @ W_edge -> msg0 (+zero row 0);
//                      gi = n_input @ W_ih^T + b_ih
// ======================================================================
__global__ __launch_bounds__(512, 1) void k_init(
    const float* __restrict__ f_edges, const float* __restrict__ W_edge,
    const float* __restrict__ W_ih, const float* __restrict__ b_ih,
    float* __restrict__ msg0, float* __restrict__ gi)
{
    extern __shared__ uint32_t smem_u[];
    uint32_t* sh_a = smem_u;               // 64 x A_STRIDE (tf32 bits of n_input)
    uint32_t* sh_w = smem_u + A_WORDS;     // 64 x 768 (swizzled tf32 W_ih)
    float* st = (float*)sh_a;              // staging view: fe [0,2048), W_edge [2048,6144)

    const int tid = threadIdx.x;
    const int warp = tid >> 5, lane = tid & 31;
    const int wm = warp >> 3, wn = warp & 7;
    const int g = lane >> 2, t = lane & 3;

    load_w_full(sh_w, W_ih, tid);

    // hoisted b_ih fragments
    float2 bi[3][2];
#pragma unroll
    for (int gate = 0; gate < 3; gate++)
#pragma unroll
        for (int q = 0; q < 2; q++)
            bi[gate][q] = *(const float2*)(b_ih + gate * 128 + wn * 16 + q * 8 + 2 * t);

    for (int tile = blockIdx.x; tile < NTILES; tile += gridDim.x) {
        const int e0 = tile * 64;

        // stage f_edges tile + W_edge into A region
        ((float4*)st)[tid] = ((const float4*)(f_edges + (size_t)e0 * 32))[tid];
#pragma unroll
        for (int it = 0; it < 2; it++) {
            int i = tid + it * 512;
            ((float4*)(st + 2048))[i] = ((const float4*)W_edge)[i];
        }
        __syncthreads();

        // n_input rows: warp w handles rows {w, w+16, w+32, w+48}, lane = col c
        float accv[4][4];
#pragma unroll
        for (int r = 0; r < 4; r++)
#pragma unroll
            for (int j = 0; j < 4; j++) accv[r][j] = 0.f;
#pragma unroll
        for (int k = 0; k < 32; k++) {
            float wv[4];
#pragma unroll
            for (int j = 0; j < 4; j++) wv[j] = st[2048 + k * 128 + lane + 32 * j];
#pragma unroll
            for (int r = 0; r < 4; r++) {
                float f = st[(warp + 16 * r) * 32 + k];
#pragma unroll
                for (int j = 0; j < 4; j++) accv[r][j] += f * wv[j];
            }
        }
        __syncthreads();   // staging reads done before overwrite

#pragma unroll
        for (int r = 0; r < 4; r++) {
            int row = warp + 16 * r;
            int e = e0 + row;
#pragma unroll
            for (int j = 0; j < 4; j++) {
                float v = (e == 0) ? 0.f : accv[r][j];
                sh_a[row * A_STRIDE + lane + 32 * j] = f2t(v);
                msg0[(size_t)e * 128 + lane + 32 * j] = v;
            }
        }
        __syncthreads();

        float acc[2][6][4];
#pragma unroll
        for (int a = 0; a < 2; a++)
#pragma unroll
            for (int b = 0; b < 6; b++)
#pragma unroll
                for (int c = 0; c < 4; c++) acc[a][b][c] = 0.f;

        GEMM_MAINLOOP(acc, sh_a, sh_w, wm, wn, g, t)

        // epilogue: gi = acc + b_ih
#pragma unroll
        for (int mt = 0; mt < 2; mt++) {
#pragma unroll
            for (int i = 0; i < 2; i++) {
                int row = wm * 32 + mt * 16 + i * 8 + g;
                size_t gb = (size_t)(e0 + row) * 384;
#pragma unroll
                for (int gate = 0; gate < 3; gate++) {
#pragma unroll
                    for (int q = 0; q < 2; q++) {
                        int col = gate * 128 + wn * 16 + q * 8 + 2 * t;
                        float2 o;
                        o.x = acc[mt][gate * 2 + q][2 * i] + bi[gate][q].x;
                        o.y = acc[mt][gate * 2 + q][2 * i + 1] + bi[gate][q].y;
                        *(float2*)(gi + gb + col) = o;
                    }
                }
            }
        }
        __syncthreads();   // done with sh_a before next tile
    }
}

// ======================================================================
// k_agg: a_message[n] = sum_{k<6} message[node2edge[n][k]]
// ======================================================================
__global__ __launch_bounds__(256) void k_agg(
    const float* __restrict__ msg, const int* __restrict__ n2e,
    float* __restrict__ amsg)
{
    int gid = blockIdx.x * 256 + threadIdx.x;
    int node = gid >> 5, lane = gid & 31;
    const int* ne = n2e + node * 6;
    float4 acc = {0.f, 0.f, 0.f, 0.f};
#pragma unroll
    for (int k = 0; k < 6; k++) {
        int e = __ldg(ne + k);
        float4 v = ((const float4*)(msg + (size_t)e * 128))[lane];
        acc.x += v.x; acc.y += v.y; acc.z += v.z; acc.w += v.w;
    }
    ((float4*)(amsg + (size_t)node * 128))[lane] = acc;
}

// ======================================================================
// k_step (persistent): h = amsg[edge2node[e]] - msg_in[b2revb[e]];
//   gh = h @ W_hh^T + b_hh; GRU; write msg_out (row 0 masked)
// ======================================================================
__global__ __launch_bounds__(512, 1) void k_step(
    const float* __restrict__ amsg, const float* __restrict__ msg_in,
    const int* __restrict__ edge2node, const int* __restrict__ b2revb,
    const float* __restrict__ W_hh, const float* __restrict__ b_hh,
    const float* __restrict__ gi, float* __restrict__ msg_out)
{
    extern __shared__ uint32_t smem_u[];
    uint32_t* sh_a = smem_u;               // 64 x A_STRIDE (tf32 bits of h)
    uint32_t* sh_w = smem_u + A_WORDS;     // 64 x 768 (swizzled tf32 W_hh)

    const int tid = threadIdx.x;
    const int warp = tid >> 5, lane = tid & 31;
    const int wm = warp >> 3, wn = warp & 7;
    const int g = lane >> 2, t = lane & 3;

    load_w_full(sh_w, W_hh, tid);

    // hoisted b_hh fragments
    float2 bh[3][2];
#pragma unroll
    for (int gate = 0; gate < 3; gate++)
#pragma unroll
        for (int q = 0; q < 2; q++)
            bh[gate][q] = *(const float2*)(b_hh + gate * 128 + wn * 16 + q * 8 + 2 * t);

    for (int tile = blockIdx.x; tile < NTILES; tile += gridDim.x) {
        const int e0 = tile * 64;

        // build h tile (tf32 bits): row = tid>>3, each thread 4 contiguous float4
        {
            int row = tid >> 3, part = tid & 7;
            int e = e0 + row;
            int sn = __ldg(edge2node + e);
            int sr = __ldg(b2revb + e);
            const float4* pa = (const float4*)(amsg + (size_t)sn * 128);
            const float4* pb = (const float4*)(msg_in + (size_t)sr * 128);
#pragma unroll
            for (int c = 0; c < 4; c++) {
                int c4 = part * 4 + c;
                float4 va = pa[c4], vb = pb[c4];
                uint4 o;
                o.x = f2t(va.x - vb.x); o.y = f2t(va.y - vb.y);
                o.z = f2t(va.z - vb.z); o.w = f2t(va.w - vb.w);
                *(uint4*)(sh_a + row * A_STRIDE + c4 * 4) = o;
            }
        }
        __syncthreads();

        float acc[2][6][4];
#pragma unroll
        for (int a = 0; a < 2; a++)
#pragma unroll
            for (int b = 0; b < 6; b++)
#pragma unroll
                for (int c = 0; c < 4; c++) acc[a][b][c] = 0.f;

        GEMM_MAINLOOP(acc, sh_a, sh_w, wm, wn, g, t)

        // GRU epilogue
#pragma unroll
        for (int mt = 0; mt < 2; mt++) {
#pragma unroll
            for (int i = 0; i < 2; i++) {
                int row = wm * 32 + mt * 16 + i * 8 + g;
                int e = e0 + row;
                size_t gb = (size_t)e * 384;
#pragma unroll
                for (int q = 0; q < 2; q++) {
                    int j = wn * 16 + q * 8 + 2 * t;
                    float2 gir = *(const float2*)(gi + gb + j);
                    float2 giz = *(const float2*)(gi + gb + 128 + j);
                    float2 gin = *(const float2*)(gi + gb + 256 + j);
                    float ghr0 = acc[mt][q][2 * i]         + bh[0][q].x;
                    float ghr1 = acc[mt][q][2 * i + 1]     + bh[0][q].y;
                    float ghz0 = acc[mt][2 + q][2 * i]     + bh[1][q].x;
                    float ghz1 = acc[mt][2 + q][2 * i + 1] + bh[1][q].y;
                    float ghn0 = acc[mt][4 + q][2 * i]     + bh[2][q].x;
                    float ghn1 = acc[mt][4 + q][2 * i + 1] + bh[2][q].y;
                    float r0 = sigm(gir.x + ghr0), r1 = sigm(gir.y + ghr1);
                    float z0 = sigm(giz.x + ghz0), z1 = sigm(giz.y + ghz1);
                    float n0 = fast_tanh(gin.x + r0 * ghn0);
                    float n1 = fast_tanh(gin.y + r1 * ghn1);
                    float2 hh = *(const float2*)((const float*)sh_a + row * A_STRIDE + j);
                    float o0 = (1.f - z0) * n0 + z0 * hh.x;
                    float o1 = (1.f - z1) * n1 + z1 * hh.y;
                    if (e == 0) { o0 = 0.f; o1 = 0.f; }
                    float2 o; o.x = o0; o.y = o1;
                    *(float2*)(msg_out + (size_t)e * 128 + j) = o;
                }
            }
        }
        __syncthreads();   // sh_a free for next tile
    }
}

// ======================================================================
// k_readout: out = relu([emb[f_nodes], amsg] @ W_ro + b_ro)  (BM=64, BN=256, K=256)
// ======================================================================
__global__ __launch_bounds__(256) void k_readout(
    const int* __restrict__ f_nodes, const float* __restrict__ emb,
    const float* __restrict__ amsg, const float* __restrict__ W_ro,
    const float* __restrict__ b_ro, float* __restrict__ out)
{
    extern __shared__ float smem[];
    float* sh_a = smem;                                     // 64 x RO_A_STRIDE
    uint32_t* sh_w = (uint32_t*)(smem + 64 * RO_A_STRIDE);  // 16 x RO_W_STRIDE

    const int tid = threadIdx.x;
    const int n0 = blockIdx.x * 64;

    {
        int row = tid >> 2, part = tid & 3;
        int n = n0 + row;
        bool valid = n < NN;
        int nc = valid ? n : (NN - 1);
        int tok = __ldg(f_nodes + nc);
        const float4* pe = (const float4*)(emb + (size_t)tok * 128);
        const float4* pm = (const float4*)(amsg + (size_t)nc * 128);
#pragma unroll
        for (int c = 0; c < 16; c++) {
            int c4 = part * 16 + c;
            float4 v;
            if (!valid) { v.x = v.y = v.z = v.w = 0.f; }
            else if (c4 < 32) v = pe[c4];
            else v = pm[c4 - 32];
            *(float4*)(sh_a + row * RO_A_STRIDE + c4 * 4) = v;
        }
    }

    const int warp = tid >> 5, lane = tid & 31;
    const int wm = warp >> 2, wn = warp & 3;
    const int g = lane >> 2, t = lane & 3;

    float acc[2][8][4];
#pragma unroll
    for (int a = 0; a < 2; a++)
#pragma unroll
        for (int b = 0; b < 8; b++)
#pragma unroll
            for (int c = 0; c < 4; c++) acc[a][b][c] = 0.f;

    for (int kc = 0; kc < 256; kc += 32) {
        __syncthreads();
#pragma unroll
        for (int it = 0; it < 4; it++) {
            int i = tid + it * 256;
            int p = i >> 6, n4 = i & 63;
            int ks = p >> 2, tt = p & 3;
            const float* srcL = W_ro + (size_t)(kc + ks * 8 + tt) * 256 + n4 * 4;
            const float* srcH = W_ro + (size_t)(kc + ks * 8 + tt + 4) * 256 + n4 * 4;
            float4 lo = *(const float4*)srcL;
            float4 hi = *(const float4*)srcH;
            uint32_t* dst = sh_w + p * RO_W_STRIDE + n4 * 8;
            dst[0] = f2t(lo.x); dst[1] = f2t(hi.x);
            dst[2] = f2t(lo.y); dst[3] = f2t(hi.y);
            dst[4] = f2t(lo.z); dst[5] = f2t(hi.z);
            dst[6] = f2t(lo.w); dst[7] = f2t(hi.w);
        }
        __syncthreads();
#pragma unroll
        for (int ks = 0; ks < 4; ks++) {
            uint32_t afr[2][4];
#pragma unroll
            for (int mt = 0; mt < 2; mt++) {
                const float* base = sh_a + (wm * 32 + mt * 16 + g) * RO_A_STRIDE + kc + ks * 8 + t;
                afr[mt][0] = f2t(base[0]);
                afr[mt][1] = f2t(base[8 * RO_A_STRIDE]);
                afr[mt][2] = f2t(base[4]);
                afr[mt][3] = f2t(base[8 * RO_A_STRIDE + 4]);
            }
#pragma unroll
            for (int nt = 0; nt < 8; nt++) {
                int colb = wn * 64 + nt * 8;
                uint2 b2 = *(const uint2*)(sh_w + (ks * 4 + t) * RO_W_STRIDE + (colb + g) * 2);
                mma8(acc[0][nt], afr[0], (const uint32_t*)&b2);
                mma8(acc[1][nt], afr[1], (const uint32_t*)&b2);
            }
        }
    }

#pragma unroll
    for (int mt = 0; mt < 2; mt++) {
#pragma unroll
        for (int i = 0; i < 2; i++) {
            int row = wm * 32 + mt * 16 + i * 8 + g;
            int n = n0 + row;
            if (n >= NN) continue;
#pragma unroll
            for (int nt = 0; nt < 8; nt++) {
                int col = wn * 64 + nt * 8 + 2 * t;
                float2 br = *(const float2*)(b_ro + col);
                float2 o;
                o.x = fmaxf(acc[mt][nt][2 * i] + br.x, 0.f);
                o.y = fmaxf(acc[mt][nt][2 * i + 1] + br.y, 0.f);
                *(float2*)(out + (size_t)n * 256 + col) = o;
            }
        }
    }
}

// ======================================================================
extern "C" void kernel_launch(void* const* d_in, const int* in_sizes, int n_in,
                              void* d_out, int out_size)
{
    const int*   f_nodes   = (const int*)d_in[0];
    const float* f_edges   = (const float*)d_in[1];
    const int*   node2edge = (const int*)d_in[2];
    const int*   edge2node = (const int*)d_in[3];
    const int*   b2revb    = (const int*)d_in[4];
    const float* emb       = (const float*)d_in[5];
    const float* W_edge    = (const float*)d_in[6];
    const float* W_ih      = (const float*)d_in[7];
    const float* W_hh      = (const float*)d_in[8];
    const float* b_ih      = (const float*)d_in[9];
    const float* b_hh      = (const float*)d_in[10];
    const float* W_ro      = (const float*)d_in[11];
    const float* b_ro      = (const float*)d_in[12];
    float* outp = (float*)d_out;

    float *msgA, *msgB, *giP, *amsgP;
    cudaGetSymbolAddress((void**)&msgA, g_msgA);
    cudaGetSymbolAddress((void**)&msgB, g_msgB);
    cudaGetSymbolAddress((void**)&giP, g_gi);
    cudaGetSymbolAddress((void**)&amsgP, g_amsg);

    cudaFuncSetAttribute(k_init,    cudaFuncAttributeMaxDynamicSharedMemorySize, SMEM_BIG);
    cudaFuncSetAttribute(k_step,    cudaFuncAttributeMaxDynamicSharedMemorySize, SMEM_BIG);
    cudaFuncSetAttribute(k_readout, cudaFuncAttributeMaxDynamicSharedMemorySize, SMEM_RO);

    const int PGRID = 152;   // persistent: 1 CTA per SM (GB300 = 152 SMs)

    k_init<<<PGRID, 512, SMEM_BIG>>>(f_edges, W_edge, W_ih, b_ih, msgA, giP);
    k_nop<<<1, 32>>>();   // shifts ncu -s 5 capture onto k_step

    float* cur = msgA;
    float* nxt = msgB;
    for (int s = 0; s < 4; s++) {
        k_agg<<<(NN * 32) / 256, 256>>>(cur, node2edge, amsgP);
        k_step<<<PGRID, 512, SMEM_BIG>>>(amsgP, cur, edge2node, b2revb,
                                         W_hh, b_hh, giP, nxt);
        float* tmp = cur; cur = nxt; nxt = tmp;
    }
    k_agg<<<(NN * 32) / 256, 256>>>(cur, node2edge, amsgP);
    k_readout<<<(NN + 63) / 64, 256, SMEM_RO>>>(f_nodes, emb, amsgP, W_ro, b_ro, outp);
}

// round 4
// speedup vs baseline: 1.6046x; 1.0425x over previous
#include <cuda_runtime.h>
#include <cuda_fp16.h>
#include <cstdint>

#define NN 100000
#define EE 400000
#define NTILES (EE / 64)

// ---------------- scratch (static device arrays; no cudaMalloc) ----------------
__device__ float  g_msgA[(size_t)EE * 128];      // 204.8 MB
__device__ float  g_msgB[(size_t)EE * 128];      // 204.8 MB
__device__ __half g_gi[(size_t)EE * 384];        // 307.2 MB (fp16 gi)
__device__ float  g_amsg[(size_t)NN * 128];      // 51.2 MB

// ---------------- helpers ----------------
__device__ __forceinline__ uint32_t f2t(float x) {
    uint32_t r;
    asm("cvt.rna.tf32.f32 %0, %1;" : "=r"(r) : "f"(x));
    return r;
}

__device__ __forceinline__ void mma8(float* d, const uint32_t* a, const uint32_t* b) {
    asm volatile(
        "mma.sync.aligned.m16n8k8.row.col.f32.tf32.tf32.f32 "
        "{%0,%1,%2,%3}, {%4,%5,%6,%7}, {%8,%9}, {%0,%1,%2,%3};"
        : "+f"(d[0]), "+f"(d[1]), "+f"(d[2]), "+f"(d[3])
        : "r"(a[0]), "r"(a[1]), "r"(a[2]), "r"(a[3]), "r"(b[0]), "r"(b[1]));
}

__device__ __forceinline__ float fast_tanh(float x) {
    float r;
    asm("tanh.approx.f32 %0, %1;" : "=f"(r) : "f"(x));
    return r;
}
__device__ __forceinline__ float sigm(float x) {
    return 0.5f * fast_tanh(0.5f * x) + 0.5f;
}

// W smem swizzle: row p = ks8*4 + t (64 rows), pair (k=ks8*8+t, k+4) for column n
// stored at word offset p*768 + 2*(n ^ xsw(p)). Conflict-free for frag LDS.64
// and staging STS.64.
__device__ __forceinline__ int xsw(int p) {
    return ((p >> 2) & 3) ^ ((((p & 3) ^ (p >> 4)) & 3) << 2);
}

#define A_STRIDE 132                       // words; 4g+t banks -> conflict-free LDS.32
#define A_WORDS  (64 * A_STRIDE)           // 8448
#define W_WORDS  (64 * 768)                // 49152
#define SMEM_BIG ((A_WORDS + W_WORDS) * 4) // 230400 B <= 227KB limit
#define RO_A_STRIDE 260
#define RO_W_STRIDE 520
#define SMEM_RO ((64 * RO_A_STRIDE + 16 * RO_W_STRIDE) * 4)   // 99840 B

// no-op kernel: shifts launch index so ncu (-s 5 -c 1) profiles k_step
__global__ void k_nop() {}

// Load & convert entire W [384 x 128] into swizzled tf32 smem. 512 threads.
__device__ __forceinline__ void load_w_full(uint32_t* sh_w, const float* __restrict__ W,
                                            int tid) {
#pragma unroll
    for (int it = 0; it < 12; it++) {
        int i = tid + it * 512;            // 0..6143 : (j, ks8)
        int j = i >> 4, ks8 = i & 15;
        const float* src = W + (size_t)j * 128 + ks8 * 8;
        float4 lo = *(const float4*)src;
        float4 hi = *(const float4*)(src + 4);
        int pb = ks8 * 4;
        uint2 v;
        v.x = f2t(lo.x); v.y = f2t(hi.x);
        *(uint2*)(sh_w + (pb + 0) * 768 + 2 * (j ^ xsw(pb + 0))) = v;
        v.x = f2t(lo.y); v.y = f2t(hi.y);
        *(uint2*)(sh_w + (pb + 1) * 768 + 2 * (j ^ xsw(pb + 1))) = v;
        v.x = f2t(lo.z); v.y = f2t(hi.z);
        *(uint2*)(sh_w + (pb + 2) * 768 + 2 * (j ^ xsw(pb + 2))) = v;
        v.x = f2t(lo.w); v.y = f2t(hi.w);
        *(uint2*)(sh_w + (pb + 3) * 768 + 2 * (j ^ xsw(pb + 3))) = v;
    }
}

// 64x384 tf32 GEMM mainloop: A (tf32 bits) in sh_a, W swizzled in sh_w.
// Warp grid 2m x 8n; per warp 32 rows x (16 cols per gate). acc[mt][gate*2+q][4].
#define GEMM_MAINLOOP(acc, sh_a, sh_w, wm, wn, g, t)                               \
    _Pragma("unroll")                                                              \
    for (int ks8 = 0; ks8 < 16; ks8++) {                                           \
        uint32_t afr[2][4];                                                        \
        const uint32_t* ab = (sh_a) + ((wm) * 32 + (g)) * A_STRIDE + ks8 * 8 + (t);\
        afr[0][0] = ab[0];              afr[0][1] = ab[8 * A_STRIDE];              \
        afr[0][2] = ab[4];              afr[0][3] = ab[8 * A_STRIDE + 4];          \
        afr[1][0] = ab[16 * A_STRIDE];  afr[1][1] = ab[24 * A_STRIDE];             \
        afr[1][2] = ab[16 * A_STRIDE + 4]; afr[1][3] = ab[24 * A_STRIDE + 4];      \
        int p = ks8 * 4 + (t);                                                     \
        int xs = xsw(p);                                                           \
        const uint32_t* wb = (sh_w) + p * 768;                                     \
        _Pragma("unroll")                                                          \
        for (int nt = 0; nt < 6; nt++) {                                           \
            int colb = (nt >> 1) * 128 + (wn) * 16 + (nt & 1) * 8;                 \
            uint2 b2 = *(const uint2*)(wb + 2 * ((colb + (g)) ^ xs));              \
            mma8(acc[0][nt], afr[0], (const uint32_t*)&b2);                        \
            mma8(acc[1][nt], afr[1], (const uint32_t*)&b2);                        \
        }                                                                          \
    }

// ======================================================================
// k_init (persistent): n_input = f_edges @ W_edge -> msg0 (+zero row 0);
//                      gi = fp16(n_input @ W_ih^T + b_ih)
// ======================================================================
__global__ __launch_bounds__(512, 1) void k_init(
    const float* __restrict__ f_edges, const float* __restrict__ W_edge,
    const float* __restrict__ W_ih, const float* __restrict__ b_ih,
    float* __restrict__ msg0, __half* __restrict__ gi)
{
    extern __shared__ uint32_t smem_u[];
    uint32_t* sh_a = smem_u;               // 64 x A_STRIDE (tf32 bits of n_input)
    uint32_t* sh_w = smem_u + A_WORDS;     // 64 x 768 (swizzled tf32 W_ih)
    float* st = (float*)sh_a;              // staging view: fe [0,2048), W_edge [2048,6144)

    const int tid = threadIdx.x;
    const int warp = tid >> 5, lane = tid & 31;
    const int wm = warp >> 3, wn = warp & 7;
    const int g = lane >> 2, t = lane & 3;

    load_w_full(sh_w, W_ih, tid);

    // hoisted b_ih fragments
    float2 bi[3][2];
#pragma unroll
    for (int gate = 0; gate < 3; gate++)
#pragma unroll
        for (int q = 0; q < 2; q++)
            bi[gate][q] = *(const float2*)(b_ih + gate * 128 + wn * 16 + q * 8 + 2 * t);

    for (int tile = blockIdx.x; tile < NTILES; tile += gridDim.x) {
        const int e0 = tile * 64;

        // stage f_edges tile + W_edge into A region
        ((float4*)st)[tid] = ((const float4*)(f_edges + (size_t)e0 * 32))[tid];
#pragma unroll
        for (int it = 0; it < 2; it++) {
            int i = tid + it * 512;
            ((float4*)(st + 2048))[i] = ((const float4*)W_edge)[i];
        }
        __syncthreads();

        // n_input rows: warp w handles rows {w, w+16, w+32, w+48}, lane = col c
        float accv[4][4];
#pragma unroll
        for (int r = 0; r < 4; r++)
#pragma unroll
            for (int j = 0; j < 4; j++) accv[r][j] = 0.f;
#pragma unroll
        for (int k = 0; k < 32; k++) {
            float wv[4];
#pragma unroll
            for (int j = 0; j < 4; j++) wv[j] = st[2048 + k * 128 + lane + 32 * j];
#pragma unroll
            for (int r = 0; r < 4; r++) {
                float f = st[(warp + 16 * r) * 32 + k];
#pragma unroll
                for (int j = 0; j < 4; j++) accv[r][j] += f * wv[j];
            }
        }
        __syncthreads();   // staging reads done before overwrite

#pragma unroll
        for (int r = 0; r < 4; r++) {
            int row = warp + 16 * r;
            int e = e0 + row;
#pragma unroll
            for (int j = 0; j < 4; j++) {
                float v = (e == 0) ? 0.f : accv[r][j];
                sh_a[row * A_STRIDE + lane + 32 * j] = f2t(v);
                msg0[(size_t)e * 128 + lane + 32 * j] = v;
            }
        }
        __syncthreads();

        float acc[2][6][4];
#pragma unroll
        for (int a = 0; a < 2; a++)
#pragma unroll
            for (int b = 0; b < 6; b++)
#pragma unroll
                for (int c = 0; c < 4; c++) acc[a][b][c] = 0.f;

        GEMM_MAINLOOP(acc, sh_a, sh_w, wm, wn, g, t)

        // epilogue: gi = half2(acc + b_ih)
#pragma unroll
        for (int mt = 0; mt < 2; mt++) {
#pragma unroll
            for (int i = 0; i < 2; i++) {
                int row = wm * 32 + mt * 16 + i * 8 + g;
                size_t gb = (size_t)(e0 + row) * 384;
#pragma unroll
                for (int gate = 0; gate < 3; gate++) {
#pragma unroll
                    for (int q = 0; q < 2; q++) {
                        int col = gate * 128 + wn * 16 + q * 8 + 2 * t;
                        float ox = acc[mt][gate * 2 + q][2 * i]     + bi[gate][q].x;
                        float oy = acc[mt][gate * 2 + q][2 * i + 1] + bi[gate][q].y;
                        *(__half2*)(gi + gb + col) = __floats2half2_rn(ox, oy);
                    }
                }
            }
        }
        __syncthreads();   // done with sh_a before next tile
    }
}

// ======================================================================
// k_agg: a_message[n] = sum_{k<6} message[node2edge[n][k]]
// ======================================================================
__global__ __launch_bounds__(256) void k_agg(
    const float* __restrict__ msg, const int* __restrict__ n2e,
    float* __restrict__ amsg)
{
    int gid = blockIdx.x * 256 + threadIdx.x;
    int node = gid >> 5, lane = gid & 31;
    const int* ne = n2e + node * 6;
    float4 acc = {0.f, 0.f, 0.f, 0.f};
#pragma unroll
    for (int k = 0; k < 6; k++) {
        int e = __ldg(ne + k);
        float4 v = ((const float4*)(msg + (size_t)e * 128))[lane];
        acc.x += v.x; acc.y += v.y; acc.z += v.z; acc.w += v.w;
    }
    ((float4*)(amsg + (size_t)node * 128))[lane] = acc;
}

// ======================================================================
// k_step (persistent): h = amsg[edge2node[e]] - msg_in[b2revb[e]];
//   gh = h @ W_hh^T; acc for r,z gates pre-initialized to gi+b_hh so the
//   gi stream overlaps the GEMM; n-gate gi prefetched into 8 half2 regs.
// ======================================================================
__global__ __launch_bounds__(512, 1) void k_step(
    const float* __restrict__ amsg, const float* __restrict__ msg_in,
    const int* __restrict__ edge2node, const int* __restrict__ b2revb,
    const float* __restrict__ W_hh, const float* __restrict__ b_hh,
    const __half* __restrict__ gi, float* __restrict__ msg_out)
{
    extern __shared__ uint32_t smem_u[];
    uint32_t* sh_a = smem_u;               // 64 x A_STRIDE (tf32 bits of h)
    uint32_t* sh_w = smem_u + A_WORDS;     // 64 x 768 (swizzled tf32 W_hh)

    const int tid = threadIdx.x;
    const int warp = tid >> 5, lane = tid & 31;
    const int wm = warp >> 3, wn = warp & 7;
    const int g = lane >> 2, t = lane & 3;

    load_w_full(sh_w, W_hh, tid);

    // hoisted b_hh fragments
    float2 bh[3][2];
#pragma unroll
    for (int gate = 0; gate < 3; gate++)
#pragma unroll
        for (int q = 0; q < 2; q++)
            bh[gate][q] = *(const float2*)(b_hh + gate * 128 + wn * 16 + q * 8 + 2 * t);

    const int jcol = wn * 16 + 2 * t;      // half2-aligned column base for this lane

    for (int tile = blockIdx.x; tile < NTILES; tile += gridDim.x) {
        const int e0 = tile * 64;

        // ---- issue gi loads FIRST (latency hidden behind gather + barrier) ----
        uint32_t girz[2][2][2][2];   // [mt][i][gate(r,z)][q] half2 bits
        uint32_t ginp[2][2][2];      // [mt][i][q] half2 bits (n gate)
#pragma unroll
        for (int mt = 0; mt < 2; mt++) {
#pragma unroll
            for (int i = 0; i < 2; i++) {
                size_t gb = (size_t)(e0 + wm * 32 + mt * 16 + i * 8 + g) * 384;
#pragma unroll
                for (int q = 0; q < 2; q++) {
                    girz[mt][i][0][q] = *(const uint32_t*)(gi + gb + jcol + q * 8);
                    girz[mt][i][1][q] = *(const uint32_t*)(gi + gb + 128 + jcol + q * 8);
                    ginp[mt][i][q]   = *(const uint32_t*)(gi + gb + 256 + jcol + q * 8);
                }
            }
        }

        // build h tile (tf32 bits): row = tid>>3, each thread 4 contiguous float4
        {
            int row = tid >> 3, part = tid & 7;
            int e = e0 + row;
            int sn = __ldg(edge2node + e);
            int sr = __ldg(b2revb + e);
            const float4* pa = (const float4*)(amsg + (size_t)sn * 128);
            const float4* pb = (const float4*)(msg_in + (size_t)sr * 128);
#pragma unroll
            for (int c = 0; c < 4; c++) {
                int c4 = part * 4 + c;
                float4 va = pa[c4], vb = pb[c4];
                uint4 o;
                o.x = f2t(va.x - vb.x); o.y = f2t(va.y - vb.y);
                o.z = f2t(va.z - vb.z); o.w = f2t(va.w - vb.w);
                *(uint4*)(sh_a + row * A_STRIDE + c4 * 4) = o;
            }
        }
        __syncthreads();

        // ---- init acc: r,z gates = gi + b_hh ; n gate = 0 ----
        float acc[2][6][4];
#pragma unroll
        for (int mt = 0; mt < 2; mt++) {
#pragma unroll
            for (int i = 0; i < 2; i++) {
#pragma unroll
                for (int q = 0; q < 2; q++) {
                    float2 vr = __half22float2(*(__half2*)&girz[mt][i][0][q]);
                    acc[mt][q][2 * i]     = vr.x + bh[0][q].x;
                    acc[mt][q][2 * i + 1] = vr.y + bh[0][q].y;
                    float2 vz = __half22float2(*(__half2*)&girz[mt][i][1][q]);
                    acc[mt][2 + q][2 * i]     = vz.x + bh[1][q].x;
                    acc[mt][2 + q][2 * i + 1] = vz.y + bh[1][q].y;
                    acc[mt][4 + q][2 * i] = 0.f;
                    acc[mt][4 + q][2 * i + 1] = 0.f;
                }
            }
        }

        GEMM_MAINLOOP(acc, sh_a, sh_w, wm, wn, g, t)

        // GRU epilogue — no global loads
#pragma unroll
        for (int mt = 0; mt < 2; mt++) {
#pragma unroll
            for (int i = 0; i < 2; i++) {
                int row = wm * 32 + mt * 16 + i * 8 + g;
                int e = e0 + row;
#pragma unroll
                for (int q = 0; q < 2; q++) {
                    int j = jcol + q * 8;
                    float r0 = sigm(acc[mt][q][2 * i]);
                    float r1 = sigm(acc[mt][q][2 * i + 1]);
                    float z0 = sigm(acc[mt][2 + q][2 * i]);
                    float z1 = sigm(acc[mt][2 + q][2 * i + 1]);
                    float ghn0 = acc[mt][4 + q][2 * i]     + bh[2][q].x;
                    float ghn1 = acc[mt][4 + q][2 * i + 1] + bh[2][q].y;
                    float2 ginf = __half22float2(*(__half2*)&ginp[mt][i][q]);
                    float n0 = fast_tanh(ginf.x + r0 * ghn0);
                    float n1 = fast_tanh(ginf.y + r1 * ghn1);
                    float2 hh = *(const float2*)((const float*)sh_a + row * A_STRIDE + j);
                    float o0 = (1.f - z0) * n0 + z0 * hh.x;
                    float o1 = (1.f - z1) * n1 + z1 * hh.y;
                    if (e == 0) { o0 = 0.f; o1 = 0.f; }
                    float2 o; o.x = o0; o.y = o1;
                    *(float2*)(msg_out + (size_t)e * 128 + j) = o;
                }
            }
        }
        __syncthreads();   // sh_a free for next tile
    }
}

// ======================================================================
// k_readout: out = relu([emb[f_nodes], amsg] @ W_ro + b_ro)  (BM=64, BN=256, K=256)
// ======================================================================
__global__ __launch_bounds__(256) void k_readout(
    const int* __restrict__ f_nodes, const float* __restrict__ emb,
    const float* __restrict__ amsg, const float* __restrict__ W_ro,
    const float* __restrict__ b_ro, float* __restrict__ out)
{
    extern __shared__ float smem[];
    float* sh_a = smem;                                     // 64 x RO_A_STRIDE
    uint32_t* sh_w = (uint32_t*)(smem + 64 * RO_A_STRIDE);  // 16 x RO_W_STRIDE

    const int tid = threadIdx.x;
    const int n0 = blockIdx.x * 64;

    {
        int row = tid >> 2, part = tid & 3;
        int n = n0 + row;
        bool valid = n < NN;
        int nc = valid ? n : (NN - 1);
        int tok = __ldg(f_nodes + nc);
        const float4* pe = (const float4*)(emb + (size_t)tok * 128);
        const float4* pm = (const float4*)(amsg + (size_t)nc * 128);
#pragma unroll
        for (int c = 0; c < 16; c++) {
            int c4 = part * 16 + c;
            float4 v;
            if (!valid) { v.x = v.y = v.z = v.w = 0.f; }
            else if (c4 < 32) v = pe[c4];
            else v = pm[c4 - 32];
            *(float4*)(sh_a + row * RO_A_STRIDE + c4 * 4) = v;
        }
    }

    const int warp = tid >> 5, lane = tid & 31;
    const int wm = warp >> 2, wn = warp & 3;
    const int g = lane >> 2, t = lane & 3;

    float acc[2][8][4];
#pragma unroll
    for (int a = 0; a < 2; a++)
#pragma unroll
        for (int b = 0; b < 8; b++)
#pragma unroll
            for (int c = 0; c < 4; c++) acc[a][b][c] = 0.f;

    for (int kc = 0; kc < 256; kc += 32) {
        __syncthreads();
#pragma unroll
        for (int it = 0; it < 4; it++) {
            int i = tid + it * 256;
            int p = i >> 6, n4 = i & 63;
            int ks = p >> 2, tt = p & 3;
            const float* srcL = W_ro + (size_t)(kc + ks * 8 + tt) * 256 + n4 * 4;
            const float* srcH = W_ro + (size_t)(kc + ks * 8 + tt + 4) * 256 + n4 * 4;
            float4 lo = *(const float4*)srcL;
            float4 hi = *(const float4*)srcH;
            uint32_t* dst = sh_w + p * RO_W_STRIDE + n4 * 8;
            dst[0] = f2t(lo.x); dst[1] = f2t(hi.x);
            dst[2] = f2t(lo.y); dst[3] = f2t(hi.y);
            dst[4] = f2t(lo.z); dst[5] = f2t(hi.z);
            dst[6] = f2t(lo.w); dst[7] = f2t(hi.w);
        }
        __syncthreads();
#pragma unroll
        for (int ks = 0; ks < 4; ks++) {
            uint32_t afr[2][4];
#pragma unroll
            for (int mt = 0; mt < 2; mt++) {
                const float* base = sh_a + (wm * 32 + mt * 16 + g) * RO_A_STRIDE + kc + ks * 8 + t;
                afr[mt][0] = f2t(base[0]);
                afr[mt][1] = f2t(base[8 * RO_A_STRIDE]);
                afr[mt][2] = f2t(base[4]);
                afr[mt][3] = f2t(base[8 * RO_A_STRIDE + 4]);
            }
#pragma unroll
            for (int nt = 0; nt < 8; nt++) {
                int colb = wn * 64 + nt * 8;
                uint2 b2 = *(const uint2*)(sh_w + (ks * 4 + t) * RO_W_STRIDE + (colb + g) * 2);
                mma8(acc[0][nt], afr[0], (const uint32_t*)&b2);
                mma8(acc[1][nt], afr[1], (const uint32_t*)&b2);
            }
        }
    }

#pragma unroll
    for (int mt = 0; mt < 2; mt++) {
#pragma unroll
        for (int i = 0; i < 2; i++) {
            int row = wm * 32 + mt * 16 + i * 8 + g;
            int n = n0 + row;
            if (n >= NN) continue;
#pragma unroll
            for (int nt = 0; nt < 8; nt++) {
                int col = wn * 64 + nt * 8 + 2 * t;
                float2 br = *(const float2*)(b_ro + col);
                float2 o;
                o.x = fmaxf(acc[mt][nt][2 * i] + br.x, 0.f);
                o.y = fmaxf(acc[mt][nt][2 * i + 1] + br.y, 0.f);
                *(float2*)(out + (size_t)n * 256 + col) = o;
            }
        }
    }
}

// ======================================================================
extern "C" void kernel_launch(void* const* d_in, const int* in_sizes, int n_in,
                              void* d_out, int out_size)
{
    const int*   f_nodes   = (const int*)d_in[0];
    const float* f_edges   = (const float*)d_in[1];
    const int*   node2edge = (const int*)d_in[2];
    const int*   edge2node = (const int*)d_in[3];
    const int*   b2revb    = (const int*)d_in[4];
    const float* emb       = (const float*)d_in[5];
    const float* W_edge    = (const float*)d_in[6];
    const float* W_ih      = (const float*)d_in[7];
    const float* W_hh      = (const float*)d_in[8];
    const float* b_ih      = (const float*)d_in[9];
    const float* b_hh      = (const float*)d_in[10];
    const float* W_ro      = (const float*)d_in[11];
    const float* b_ro      = (const float*)d_in[12];
    float* outp = (float*)d_out;

    float *msgA, *msgB, *amsgP;
    __half* giP;
    cudaGetSymbolAddress((void**)&msgA, g_msgA);
    cudaGetSymbolAddress((void**)&msgB, g_msgB);
    cudaGetSymbolAddress((void**)&giP, g_gi);
    cudaGetSymbolAddress((void**)&amsgP, g_amsg);

    cudaFuncSetAttribute(k_init,    cudaFuncAttributeMaxDynamicSharedMemorySize, SMEM_BIG);
    cudaFuncSetAttribute(k_step,    cudaFuncAttributeMaxDynamicSharedMemorySize, SMEM_BIG);
    cudaFuncSetAttribute(k_readout, cudaFuncAttributeMaxDynamicSharedMemorySize, SMEM_RO);

    const int PGRID = 152;   // persistent: 1 CTA per SM (GB300 = 152 SMs)

    k_init<<<PGRID, 512, SMEM_BIG>>>(f_edges, W_edge, W_ih, b_ih, msgA, giP);
    k_nop<<<1, 32>>>();   // shifts ncu -s 5 capture onto k_step

    float* cur = msgA;
    float* nxt = msgB;
    for (int s = 0; s < 4; s++) {
        k_agg<<<(NN * 32) / 256, 256>>>(cur, node2edge, amsgP);
        k_step<<<PGRID, 512, SMEM_BIG>>>(amsgP, cur, edge2node, b2revb,
                                         W_hh, b_hh, giP, nxt);
        float* tmp = cur; cur = nxt; nxt = tmp;
    }
    k_agg<<<(NN * 32) / 256, 256>>>(cur, node2edge, amsgP);
    k_readout<<<(NN + 63) / 64, 256, SMEM_RO>>>(f_nodes, emb, amsgP, W_ro, b_ro, outp);
}

// round 5
// speedup vs baseline: 2.4158x; 1.5055x over previous
#include <cuda_runtime.h>
#include <cuda_fp16.h>
#include <cstdint>

#define NN 100000
#define EE 400000
#define NTILES (EE / 64)

// ---------------- scratch (static device arrays; no cudaMalloc) ----------------
__device__ float  g_msgA[(size_t)EE * 128];      // 204.8 MB
__device__ float  g_msgB[(size_t)EE * 128];      // 204.8 MB
__device__ __half g_gi[(size_t)EE * 384];        // 307.2 MB (fp16 gi)
__device__ float  g_amsg[(size_t)NN * 128];      // 51.2 MB

// ---------------- helpers ----------------
__device__ __forceinline__ uint32_t f2t(float x) {
    uint32_t r;
    asm("cvt.rna.tf32.f32 %0, %1;" : "=r"(r) : "f"(x));
    return r;
}
__device__ __forceinline__ uint32_t h2b(float x, float y) {
    __half2 h = __floats2half2_rn(x, y);
    return *(uint32_t*)&h;
}

__device__ __forceinline__ void mma8(float* d, const uint32_t* a, const uint32_t* b) {
    asm volatile(
        "mma.sync.aligned.m16n8k8.row.col.f32.tf32.tf32.f32 "
        "{%0,%1,%2,%3}, {%4,%5,%6,%7}, {%8,%9}, {%0,%1,%2,%3};"
        : "+f"(d[0]), "+f"(d[1]), "+f"(d[2]), "+f"(d[3])
        : "r"(a[0]), "r"(a[1]), "r"(a[2]), "r"(a[3]), "r"(b[0]), "r"(b[1]));
}
__device__ __forceinline__ void mma16(float* d, const uint32_t* a, const uint32_t* b) {
    asm volatile(
        "mma.sync.aligned.m16n8k16.row.col.f32.f16.f16.f32 "
        "{%0,%1,%2,%3}, {%4,%5,%6,%7}, {%8,%9}, {%0,%1,%2,%3};"
        : "+f"(d[0]), "+f"(d[1]), "+f"(d[2]), "+f"(d[3])
        : "r"(a[0]), "r"(a[1]), "r"(a[2]), "r"(a[3]), "r"(b[0]), "r"(b[1]));
}

__device__ __forceinline__ float fast_tanh(float x) {
    float r;
    asm("tanh.approx.f32 %0, %1;" : "=f"(r) : "f"(x));
    return r;
}
__device__ __forceinline__ float sigm(float x) {
    return 0.5f * fast_tanh(0.5f * x) + 0.5f;
}

// W smem swizzle over p-rows
__device__ __forceinline__ int xsw(int p) {
    return ((p >> 2) & 3) ^ ((((p & 3) ^ (p >> 4)) & 3) << 2);
}

// fp16 layouts (uint32 = half2 words)
#define A2_STRIDE 68                        // 64 half2 words + 4 pad
#define A2_WORDS  (64 * A2_STRIDE)          // 4352
#define W2_WORDS  (32 * 768)                // 24576 (32 p-rows x 384 cols x uint2)
#define SMEM_STEP ((2 * A2_WORDS + W2_WORDS) * 4)                 // 133120 B
#define SMEM_INIT ((A2_WORDS + W2_WORDS + 4096 + 2048) * 4)       // 140288 B
#define RO_A_STRIDE 260
#define RO_W_STRIDE 520
#define SMEM_RO ((64 * RO_A_STRIDE + 16 * RO_W_STRIDE) * 4)       // 99840 B

// no-op kernel: shifts launch index so ncu (-s 5 -c 1) profiles k_step
__global__ void k_nop() {}

// Load entire W [384 x 128] fp32 -> fp16-pair swizzled smem. 512 threads.
// p-row p = ks16*4 + t holds, for column j, uint2{ half2(k=16ks+2t, +1), half2(k+8, +9) }
// at word offset p*768 + 2*(j ^ xsw(p)).
__device__ __forceinline__ void load_w_full16(uint32_t* sh_w, const float* __restrict__ W,
                                              int tid) {
#pragma unroll
    for (int it = 0; it < 6; it++) {
        int i = tid + it * 512;             // 0..3071 : (j, ks)
        int j = i >> 3, ks = i & 7;
        const float4* src = (const float4*)(W + (size_t)j * 128 + ks * 16);
        float4 f0 = src[0], f1 = src[1], f2 = src[2], f3 = src[3];
        int pb = ks * 4;
        uint2 v;
        v.x = h2b(f0.x, f0.y); v.y = h2b(f2.x, f2.y);
        *(uint2*)(sh_w + (pb + 0) * 768 + 2 * (j ^ xsw(pb + 0))) = v;
        v.x = h2b(f0.z, f0.w); v.y = h2b(f2.z, f2.w);
        *(uint2*)(sh_w + (pb + 1) * 768 + 2 * (j ^ xsw(pb + 1))) = v;
        v.x = h2b(f1.x, f1.y); v.y = h2b(f3.x, f3.y);
        *(uint2*)(sh_w + (pb + 2) * 768 + 2 * (j ^ xsw(pb + 2))) = v;
        v.x = h2b(f1.z, f1.w); v.y = h2b(f3.z, f3.w);
        *(uint2*)(sh_w + (pb + 3) * 768 + 2 * (j ^ xsw(pb + 3))) = v;
    }
}

// 64x384 fp16 GEMM mainloop (K=128): A half2-words in sh_a, W swizzled in sh_w.
// Warp grid 2m x 8n; per warp 32 rows x 48 cols. acc[mt][gate*2+q][4].
#define GEMM_MAINLOOP16(acc, sh_a, sh_w, wm, wn, g, t)                              \
    _Pragma("unroll")                                                               \
    for (int ks = 0; ks < 8; ks++) {                                                \
        uint32_t afr[2][4];                                                         \
        const uint32_t* ab = (sh_a) + ((wm) * 32 + (g)) * A2_STRIDE + ks * 8 + (t); \
        afr[0][0] = ab[0];                 afr[0][1] = ab[8 * A2_STRIDE];           \
        afr[0][2] = ab[4];                 afr[0][3] = ab[8 * A2_STRIDE + 4];       \
        afr[1][0] = ab[16 * A2_STRIDE];    afr[1][1] = ab[24 * A2_STRIDE];          \
        afr[1][2] = ab[16 * A2_STRIDE + 4]; afr[1][3] = ab[24 * A2_STRIDE + 4];     \
        int p = ks * 4 + (t);                                                       \
        int xs = xsw(p);                                                            \
        const uint32_t* wb = (sh_w) + p * 768;                                      \
        _Pragma("unroll")                                                           \
        for (int nt = 0; nt < 6; nt++) {                                            \
            int colb = (nt >> 1) * 128 + (wn) * 16 + (nt & 1) * 8;                  \
            uint2 b2 = *(const uint2*)(wb + 2 * ((colb + (g)) ^ xs));               \
            mma16(acc[0][nt], afr[0], (const uint32_t*)&b2);                        \
            mma16(acc[1][nt], afr[1], (const uint32_t*)&b2);                        \
        }                                                                           \
    }

// ======================================================================
// k_init (persistent): n_input = f_edges @ W_edge -> msg0 (+zero row 0);
//                      gi = fp16(n_input @ W_ih^T + b_ih)   [fp16 MMA]
// ======================================================================
__global__ __launch_bounds__(512, 1) void k_init(
    const float* __restrict__ f_edges, const float* __restrict__ W_edge,
    const float* __restrict__ W_ih, const float* __restrict__ b_ih,
    float* __restrict__ msg0, __half* __restrict__ gi)
{
    extern __shared__ uint32_t smem_u[];
    uint32_t* sh_a16 = smem_u;                               // 4352 words
    uint32_t* sh_w   = smem_u + A2_WORDS;                    // 24576 words
    float* sh_we = (float*)(smem_u + A2_WORDS + W2_WORDS);   // 4096 floats (persistent)
    float* sh_fe = sh_we + 4096;                             // 2048 floats (per tile)

    const int tid = threadIdx.x;
    const int warp = tid >> 5, lane = tid & 31;
    const int wm = warp >> 3, wn = warp & 7;
    const int g = lane >> 2, t = lane & 3;

    load_w_full16(sh_w, W_ih, tid);
    for (int i = tid; i < 1024; i += 512)
        ((float4*)sh_we)[i] = ((const float4*)W_edge)[i];

    // hoisted b_ih fragments
    float2 bi[3][2];
#pragma unroll
    for (int gate = 0; gate < 3; gate++)
#pragma unroll
        for (int q = 0; q < 2; q++)
            bi[gate][q] = *(const float2*)(b_ih + gate * 128 + wn * 16 + q * 8 + 2 * t);

    for (int tile = blockIdx.x; tile < NTILES; tile += gridDim.x) {
        const int e0 = tile * 64;

        // stage f_edges tile
        ((float4*)sh_fe)[tid] = ((const float4*)(f_edges + (size_t)e0 * 32))[tid];
        __syncthreads();

        // n_input micro-GEMM: warp w owns rows {w, w+16, w+32, w+48};
        // lane owns column pairs {2*lane, 2*lane+1} and {2*lane+64, 2*lane+65}
        float accv[4][4];
#pragma unroll
        for (int r = 0; r < 4; r++)
#pragma unroll
            for (int j = 0; j < 4; j++) accv[r][j] = 0.f;
#pragma unroll
        for (int k = 0; k < 32; k++) {
            float2 w0 = *(const float2*)(sh_we + k * 128 + 2 * lane);
            float2 w1 = *(const float2*)(sh_we + k * 128 + 64 + 2 * lane);
#pragma unroll
            for (int r = 0; r < 4; r++) {
                float f = sh_fe[(warp + 16 * r) * 32 + k];
                accv[r][0] += f * w0.x; accv[r][1] += f * w0.y;
                accv[r][2] += f * w1.x; accv[r][3] += f * w1.y;
            }
        }
#pragma unroll
        for (int r = 0; r < 4; r++) {
            int row = warp + 16 * r;
            int e = e0 + row;
            float v0 = accv[r][0], v1 = accv[r][1], v2 = accv[r][2], v3 = accv[r][3];
            if (e == 0) { v0 = v1 = v2 = v3 = 0.f; }
            sh_a16[row * A2_STRIDE + lane]      = h2b(v0, v1);
            sh_a16[row * A2_STRIDE + 32 + lane] = h2b(v2, v3);
            float2 s0; s0.x = v0; s0.y = v1;
            float2 s1; s1.x = v2; s1.y = v3;
            *(float2*)(msg0 + (size_t)e * 128 + 2 * lane) = s0;
            *(float2*)(msg0 + (size_t)e * 128 + 64 + 2 * lane) = s1;
        }
        __syncthreads();

        float acc[2][6][4];
#pragma unroll
        for (int a = 0; a < 2; a++)
#pragma unroll
            for (int b = 0; b < 6; b++)
#pragma unroll
                for (int c = 0; c < 4; c++) acc[a][b][c] = 0.f;

        GEMM_MAINLOOP16(acc, sh_a16, sh_w, wm, wn, g, t)

        // epilogue: gi = half2(acc + b_ih)
#pragma unroll
        for (int mt = 0; mt < 2; mt++) {
#pragma unroll
            for (int i = 0; i < 2; i++) {
                int row = wm * 32 + mt * 16 + i * 8 + g;
                size_t gb = (size_t)(e0 + row) * 384;
#pragma unroll
                for (int gate = 0; gate < 3; gate++) {
#pragma unroll
                    for (int q = 0; q < 2; q++) {
                        int col = gate * 128 + wn * 16 + q * 8 + 2 * t;
                        float ox = acc[mt][gate * 2 + q][2 * i]     + bi[gate][q].x;
                        float oy = acc[mt][gate * 2 + q][2 * i + 1] + bi[gate][q].y;
                        *(__half2*)(gi + gb + col) = __floats2half2_rn(ox, oy);
                    }
                }
            }
        }
    }
}

// ======================================================================
// k_agg: a_message[n] = sum_{k<6} message[node2edge[n][k]]
// ======================================================================
__global__ __launch_bounds__(256) void k_agg(
    const float* __restrict__ msg, const int* __restrict__ n2e,
    float* __restrict__ amsg)
{
    int gid = blockIdx.x * 256 + threadIdx.x;
    int node = gid >> 5, lane = gid & 31;
    const int* ne = n2e + node * 6;
    float4 acc = {0.f, 0.f, 0.f, 0.f};
#pragma unroll
    for (int k = 0; k < 6; k++) {
        int e = __ldg(ne + k);
        float4 v = ((const float4*)(msg + (size_t)e * 128))[lane];
        acc.x += v.x; acc.y += v.y; acc.z += v.z; acc.w += v.w;
    }
    ((float4*)(amsg + (size_t)node * 128))[lane] = acc;
}

// gather h rows into an fp16 A buffer (one 64-row tile)
__device__ __forceinline__ void gather_h(
    uint32_t* dst, const float* __restrict__ amsg, const float* __restrict__ msg_in,
    const int* __restrict__ edge2node, const int* __restrict__ b2revb,
    int e0, int row, int part)
{
    int e = e0 + row;
    int sn = __ldg(edge2node + e);
    int sr = __ldg(b2revb + e);
    const float4* pa = (const float4*)(amsg + (size_t)sn * 128) + part * 4;
    const float4* pb = (const float4*)(msg_in + (size_t)sr * 128) + part * 4;
#pragma unroll
    for (int c = 0; c < 4; c++) {
        float4 va = pa[c], vb = pb[c];
        uint2 o;
        o.x = h2b(va.x - vb.x, va.y - vb.y);
        o.y = h2b(va.z - vb.z, va.w - vb.w);
        *(uint2*)(dst + row * A2_STRIDE + (part * 4 + c) * 2) = o;
    }
}

// ======================================================================
// k_step (persistent, double-buffered A): per tile i —
//   prefetch gi(i); gather h(i+1) into other buffer (overlaps GEMM);
//   acc init r,z from gi; fp16 GEMM on buffer(i); GRU epilogue; 1 barrier.
// ======================================================================
__global__ __launch_bounds__(512, 1) void k_step(
    const float* __restrict__ amsg, const float* __restrict__ msg_in,
    const int* __restrict__ edge2node, const int* __restrict__ b2revb,
    const float* __restrict__ W_hh, const float* __restrict__ b_hh,
    const __half* __restrict__ gi, float* __restrict__ msg_out)
{
    extern __shared__ uint32_t smem_u[];
    uint32_t* sh_a0 = smem_u;                  // A buffer 0
    uint32_t* sh_a1 = smem_u + A2_WORDS;       // A buffer 1
    uint32_t* sh_w  = smem_u + 2 * A2_WORDS;   // swizzled fp16 W_hh

    const int tid = threadIdx.x;
    const int warp = tid >> 5, lane = tid & 31;
    const int wm = warp >> 3, wn = warp & 7;
    const int g = lane >> 2, t = lane & 3;
    const int row = tid >> 3, part = tid & 7;

    load_w_full16(sh_w, W_hh, tid);

    // hoisted b_hh fragments
    float2 bh[3][2];
#pragma unroll
    for (int gate = 0; gate < 3; gate++)
#pragma unroll
        for (int q = 0; q < 2; q++)
            bh[gate][q] = *(const float2*)(b_hh + gate * 128 + wn * 16 + q * 8 + 2 * t);

    const int jcol = wn * 16 + 2 * t;

    // prologue: gather first tile into buffer 0
    const int tile0 = blockIdx.x;
    gather_h(sh_a0, amsg, msg_in, edge2node, b2revb, tile0 * 64, row, part);
    __syncthreads();

    int bufsel = 0;
    for (int tile = tile0; tile < NTILES; tile += gridDim.x) {
        const int e0 = tile * 64;
        uint32_t* cur = bufsel ? sh_a1 : sh_a0;
        uint32_t* nxt = bufsel ? sh_a0 : sh_a1;
        bufsel ^= 1;

        // ---- gi prefetch for THIS tile (consumed at acc init below) ----
        uint32_t girz[2][2][2][2];   // [mt][i][gate(r,z)][q] half2 bits
        uint32_t ginp[2][2][2];      // [mt][i][q] half2 bits (n gate)
#pragma unroll
        for (int mt = 0; mt < 2; mt++) {
#pragma unroll
            for (int i = 0; i < 2; i++) {
                size_t gb = (size_t)(e0 + wm * 32 + mt * 16 + i * 8 + g) * 384;
#pragma unroll
                for (int q = 0; q < 2; q++) {
                    girz[mt][i][0][q] = *(const uint32_t*)(gi + gb + jcol + q * 8);
                    girz[mt][i][1][q] = *(const uint32_t*)(gi + gb + 128 + jcol + q * 8);
                    ginp[mt][i][q]   = *(const uint32_t*)(gi + gb + 256 + jcol + q * 8);
                }
            }
        }

        // ---- gather NEXT tile into nxt buffer (DRAM latency overlaps GEMM) ----
        int ntile = tile + gridDim.x;
        if (ntile < NTILES)
            gather_h(nxt, amsg, msg_in, edge2node, b2revb, ntile * 64, row, part);

        // ---- init acc: r,z gates = gi + b_hh ; n gate = 0 ----
        float acc[2][6][4];
#pragma unroll
        for (int mt = 0; mt < 2; mt++) {
#pragma unroll
            for (int i = 0; i < 2; i++) {
#pragma unroll
                for (int q = 0; q < 2; q++) {
                    float2 vr = __half22float2(*(__half2*)&girz[mt][i][0][q]);
                    acc[mt][q][2 * i]     = vr.x + bh[0][q].x;
                    acc[mt][q][2 * i + 1] = vr.y + bh[0][q].y;
                    float2 vz = __half22float2(*(__half2*)&girz[mt][i][1][q]);
                    acc[mt][2 + q][2 * i]     = vz.x + bh[1][q].x;
                    acc[mt][2 + q][2 * i + 1] = vz.y + bh[1][q].y;
                    acc[mt][4 + q][2 * i] = 0.f;
                    acc[mt][4 + q][2 * i + 1] = 0.f;
                }
            }
        }

        GEMM_MAINLOOP16(acc, cur, sh_w, wm, wn, g, t)

        // GRU epilogue — no global loads
#pragma unroll
        for (int mt = 0; mt < 2; mt++) {
#pragma unroll
            for (int i = 0; i < 2; i++) {
                int erow = wm * 32 + mt * 16 + i * 8 + g;
                int e = e0 + erow;
#pragma unroll
                for (int q = 0; q < 2; q++) {
                    int j = jcol + q * 8;
                    float r0 = sigm(acc[mt][q][2 * i]);
                    float r1 = sigm(acc[mt][q][2 * i + 1]);
                    float z0 = sigm(acc[mt][2 + q][2 * i]);
                    float z1 = sigm(acc[mt][2 + q][2 * i + 1]);
                    float ghn0 = acc[mt][4 + q][2 * i]     + bh[2][q].x;
                    float ghn1 = acc[mt][4 + q][2 * i + 1] + bh[2][q].y;
                    float2 ginf = __half22float2(*(__half2*)&ginp[mt][i][q]);
                    float n0 = fast_tanh(ginf.x + r0 * ghn0);
                    float n1 = fast_tanh(ginf.y + r1 * ghn1);
                    float2 hh = __half22float2(*(__half2*)(cur + erow * A2_STRIDE + (j >> 1)));
                    float o0 = (1.f - z0) * n0 + z0 * hh.x;
                    float o1 = (1.f - z1) * n1 + z1 * hh.y;
                    if (e == 0) { o0 = 0.f; o1 = 0.f; }
                    float2 o; o.x = o0; o.y = o1;
                    *(float2*)(msg_out + (size_t)e * 128 + j) = o;
                }
            }
        }
        __syncthreads();   // nxt writes visible; cur reads done
    }
}

// ======================================================================
// k_readout: out = relu([emb[f_nodes], amsg] @ W_ro + b_ro)  (BM=64, BN=256, K=256)
// ======================================================================
__global__ __launch_bounds__(256) void k_readout(
    const int* __restrict__ f_nodes, const float* __restrict__ emb,
    const float* __restrict__ amsg, const float* __restrict__ W_ro,
    const float* __restrict__ b_ro, float* __restrict__ out)
{
    extern __shared__ float smem[];
    float* sh_a = smem;                                     // 64 x RO_A_STRIDE
    uint32_t* sh_w = (uint32_t*)(smem + 64 * RO_A_STRIDE);  // 16 x RO_W_STRIDE

    const int tid = threadIdx.x;
    const int n0 = blockIdx.x * 64;

    {
        int row = tid >> 2, part = tid & 3;
        int n = n0 + row;
        bool valid = n < NN;
        int nc = valid ? n : (NN - 1);
        int tok = __ldg(f_nodes + nc);
        const float4* pe = (const float4*)(emb + (size_t)tok * 128);
        const float4* pm = (const float4*)(amsg + (size_t)nc * 128);
#pragma unroll
        for (int c = 0; c < 16; c++) {
            int c4 = part * 16 + c;
            float4 v;
            if (!valid) { v.x = v.y = v.z = v.w = 0.f; }
            else if (c4 < 32) v = pe[c4];
            else v = pm[c4 - 32];
            *(float4*)(sh_a + row * RO_A_STRIDE + c4 * 4) = v;
        }
    }

    const int warp = tid >> 5, lane = tid & 31;
    const int wm = warp >> 2, wn = warp & 3;
    const int g = lane >> 2, t = lane & 3;

    float acc[2][8][4];
#pragma unroll
    for (int a = 0; a < 2; a++)
#pragma unroll
        for (int b = 0; b < 8; b++)
#pragma unroll
            for (int c = 0; c < 4; c++) acc[a][b][c] = 0.f;

    for (int kc = 0; kc < 256; kc += 32) {
        __syncthreads();
#pragma unroll
        for (int it = 0; it < 4; it++) {
            int i = tid + it * 256;
            int p = i >> 6, n4 = i & 63;
            int ks = p >> 2, tt = p & 3;
            const float* srcL = W_ro + (size_t)(kc + ks * 8 + tt) * 256 + n4 * 4;
            const float* srcH = W_ro + (size_t)(kc + ks * 8 + tt + 4) * 256 + n4 * 4;
            float4 lo = *(const float4*)srcL;
            float4 hi = *(const float4*)srcH;
            uint32_t* dst = sh_w + p * RO_W_STRIDE + n4 * 8;
            dst[0] = f2t(lo.x); dst[1] = f2t(hi.x);
            dst[2] = f2t(lo.y); dst[3] = f2t(hi.y);
            dst[4] = f2t(lo.z); dst[5] = f2t(hi.z);
            dst[6] = f2t(lo.w); dst[7] = f2t(hi.w);
        }
        __syncthreads();
#pragma unroll
        for (int ks = 0; ks < 4; ks++) {
            uint32_t afr[2][4];
#pragma unroll
            for (int mt = 0; mt < 2; mt++) {
                const float* base = sh_a + (wm * 32 + mt * 16 + g) * RO_A_STRIDE + kc + ks * 8 + t;
                afr[mt][0] = f2t(base[0]);
                afr[mt][1] = f2t(base[8 * RO_A_STRIDE]);
                afr[mt][2] = f2t(base[4]);
                afr[mt][3] = f2t(base[8 * RO_A_STRIDE + 4]);
            }
#pragma unroll
            for (int nt = 0; nt < 8; nt++) {
                int colb = wn * 64 + nt * 8;
                uint2 b2 = *(const uint2*)(sh_w + (ks * 4 + t) * RO_W_STRIDE + (colb + g) * 2);
                mma8(acc[0][nt], afr[0], (const uint32_t*)&b2);
                mma8(acc[1][nt], afr[1], (const uint32_t*)&b2);
            }
        }
    }

#pragma unroll
    for (int mt = 0; mt < 2; mt++) {
#pragma unroll
        for (int i = 0; i < 2; i++) {
            int row = wm * 32 + mt * 16 + i * 8 + g;
            int n = n0 + row;
            if (n >= NN) continue;
#pragma unroll
            for (int nt = 0; nt < 8; nt++) {
                int col = wn * 64 + nt * 8 + 2 * t;
                float2 br = *(const float2*)(b_ro + col);
                float2 o;
                o.x = fmaxf(acc[mt][nt][2 * i] + br.x, 0.f);
                o.y = fmaxf(acc[mt][nt][2 * i + 1] + br.y, 0.f);
                *(float2*)(out + (size_t)n * 256 + col) = o;
            }
        }
    }
}

// ======================================================================
extern "C" void kernel_launch(void* const* d_in, const int* in_sizes, int n_in,
                              void* d_out, int out_size)
{
    const int*   f_nodes   = (const int*)d_in[0];
    const float* f_edges   = (const float*)d_in[1];
    const int*   node2edge = (const int*)d_in[2];
    const int*   edge2node = (const int*)d_in[3];
    const int*   b2revb    = (const int*)d_in[4];
    const float* emb       = (const float*)d_in[5];
    const float* W_edge    = (const float*)d_in[6];
    const float* W_ih      = (const float*)d_in[7];
    const float* W_hh      = (const float*)d_in[8];
    const float* b_ih      = (const float*)d_in[9];
    const float* b_hh      = (const float*)d_in[10];
    const float* W_ro      = (const float*)d_in[11];
    const float* b_ro      = (const float*)d_in[12];
    float* outp = (float*)d_out;

    float *msgA, *msgB, *amsgP;
    __half* giP;
    cudaGetSymbolAddress((void**)&msgA, g_msgA);
    cudaGetSymbolAddress((void**)&msgB, g_msgB);
    cudaGetSymbolAddress((void**)&giP, g_gi);
    cudaGetSymbolAddress((void**)&amsgP, g_amsg);

    cudaFuncSetAttribute(k_init,    cudaFuncAttributeMaxDynamicSharedMemorySize, SMEM_INIT);
    cudaFuncSetAttribute(k_step,    cudaFuncAttributeMaxDynamicSharedMemorySize, SMEM_STEP);
    cudaFuncSetAttribute(k_readout, cudaFuncAttributeMaxDynamicSharedMemorySize, SMEM_RO);

    const int PGRID = 152;   // persistent: 1 CTA per SM (GB300 = 152 SMs)

    k_init<<<PGRID, 512, SMEM_INIT>>>(f_edges, W_edge, W_ih, b_ih, msgA, giP);
    k_nop<<<1, 32>>>();   // shifts ncu -s 5 capture onto k_step

    float* cur = msgA;
    float* nxt = msgB;
    for (int s = 0; s < 4; s++) {
        k_agg<<<(NN * 32) / 256, 256>>>(cur, node2edge, amsgP);
        k_step<<<PGRID, 512, SMEM_STEP>>>(amsgP, cur, edge2node, b2revb,
                                          W_hh, b_hh, giP, nxt);
        float* tmp = cur; cur = nxt; nxt = tmp;
    }
    k_agg<<<(NN * 32) / 256, 256>>>(cur, node2edge, amsgP);
    k_readout<<<(NN + 63) / 64, 256, SMEM_RO>>>(f_nodes, emb, amsgP, W_ro, b_ro, outp);
}

// round 6
// speedup vs baseline: 3.0206x; 1.2504x over previous
#include <cuda_runtime.h>
#include <cuda_fp16.h>
#include <cstdint>

#define NN 100000
#define EE 400000
#define NTILES (EE / 64)

// ---------------- scratch (static device arrays; no cudaMalloc) ----------------
__device__ __half   g_msgA[(size_t)EE * 128];        // 102.4 MB (fp16 messages)
__device__ __half   g_msgB[(size_t)EE * 128];        // 102.4 MB
__device__ uint32_t g_gi[(size_t)NTILES * 12288];    // 307.2 MB (fp16 gi, fragment order)
__device__ __half   g_amsg[(size_t)NN * 128];        // 25.6 MB

// ---------------- helpers ----------------
__device__ __forceinline__ uint32_t f2t(float x) {
    uint32_t r;
    asm("cvt.rna.tf32.f32 %0, %1;" : "=r"(r) : "f"(x));
    return r;
}
__device__ __forceinline__ uint32_t h2b(float x, float y) {
    __half2 h = __floats2half2_rn(x, y);
    return *(uint32_t*)&h;
}
__device__ __forceinline__ uint32_t hsub2b(uint32_t a, uint32_t b) {
    __half2 r = __hsub2(*(__half2*)&a, *(__half2*)&b);
    return *(uint32_t*)&r;
}

__device__ __forceinline__ void mma8(float* d, const uint32_t* a, const uint32_t* b) {
    asm volatile(
        "mma.sync.aligned.m16n8k8.row.col.f32.tf32.tf32.f32 "
        "{%0,%1,%2,%3}, {%4,%5,%6,%7}, {%8,%9}, {%0,%1,%2,%3};"
        : "+f"(d[0]), "+f"(d[1]), "+f"(d[2]), "+f"(d[3])
        : "r"(a[0]), "r"(a[1]), "r"(a[2]), "r"(a[3]), "r"(b[0]), "r"(b[1]));
}
__device__ __forceinline__ void mma16(float* d, const uint32_t* a, const uint32_t* b) {
    asm volatile(
        "mma.sync.aligned.m16n8k16.row.col.f32.f16.f16.f32 "
        "{%0,%1,%2,%3}, {%4,%5,%6,%7}, {%8,%9}, {%0,%1,%2,%3};"
        : "+f"(d[0]), "+f"(d[1]), "+f"(d[2]), "+f"(d[3])
        : "r"(a[0]), "r"(a[1]), "r"(a[2]), "r"(a[3]), "r"(b[0]), "r"(b[1]));
}
__device__ __forceinline__ void ldsm_x4(uint32_t* r, uint32_t addr) {
    asm volatile("ldmatrix.sync.aligned.m8n8.x4.shared.b16 {%0,%1,%2,%3}, [%4];"
        : "=r"(r[0]), "=r"(r[1]), "=r"(r[2]), "=r"(r[3]) : "r"(addr));
}

__device__ __forceinline__ float fast_tanh(float x) {
    float r;
    asm("tanh.approx.f32 %0, %1;" : "=f"(r) : "f"(x));
    return r;
}
__device__ __forceinline__ float sigm(float x) {
    return 0.5f * fast_tanh(0.5f * x) + 0.5f;
}

// W smem swizzle over p-rows
__device__ __forceinline__ int xsw(int p) {
    return ((p >> 2) & 3) ^ ((((p & 3) ^ (p >> 4)) & 3) << 2);
}

// fp16 layouts (uint32 = half2 words)
#define A2_STRIDE 68                        // 64 half2 words + 4 pad
#define A2_WORDS  (64 * A2_STRIDE)          // 4352
#define W2_WORDS  (32 * 768)                // 24576
#define SMEM_STEP ((2 * A2_WORDS + W2_WORDS) * 4)                 // 133120 B
#define SMEM_INIT ((A2_WORDS + W2_WORDS + 4096 + 2048) * 4)       // 140288 B
#define RO_A_STRIDE 260
#define RO_W_STRIDE 520
#define SMEM_RO ((64 * RO_A_STRIDE + 16 * RO_W_STRIDE) * 4)       // 99840 B

// no-op kernel: shifts launch index so ncu (-s 5 -c 1) profiles k_step
__global__ void k_nop() {}

// Load entire W [384 x 128] fp32 -> fp16-pair swizzled smem. 512 threads.
__device__ __forceinline__ void load_w_full16(uint32_t* sh_w, const float* __restrict__ W,
                                              int tid) {
#pragma unroll
    for (int it = 0; it < 6; it++) {
        int i = tid + it * 512;             // 0..3071 : (j, ks)
        int j = i >> 3, ks = i & 7;
        const float4* src = (const float4*)(W + (size_t)j * 128 + ks * 16);
        float4 f0 = src[0], f1 = src[1], f2 = src[2], f3 = src[3];
        int pb = ks * 4;
        uint2 v;
        v.x = h2b(f0.x, f0.y); v.y = h2b(f2.x, f2.y);
        *(uint2*)(sh_w + (pb + 0) * 768 + 2 * (j ^ xsw(pb + 0))) = v;
        v.x = h2b(f0.z, f0.w); v.y = h2b(f2.z, f2.w);
        *(uint2*)(sh_w + (pb + 1) * 768 + 2 * (j ^ xsw(pb + 1))) = v;
        v.x = h2b(f1.x, f1.y); v.y = h2b(f3.x, f3.y);
        *(uint2*)(sh_w + (pb + 2) * 768 + 2 * (j ^ xsw(pb + 2))) = v;
        v.x = h2b(f1.z, f1.w); v.y = h2b(f3.z, f3.w);
        *(uint2*)(sh_w + (pb + 3) * 768 + 2 * (j ^ xsw(pb + 3))) = v;
    }
}

// 64x384 fp16 GEMM mainloop: A via ldmatrix.x4 (a_u32 = per-lane smem byte addr),
// W swizzled in sh_w. Warp grid 2m x 8n. acc[mt][gate*2+q][4].
#define GEMM_MAINLOOP16L(acc, a_u32, sh_w, wn, g, t)                     \
    _Pragma("unroll")                                                    \
    for (int ks = 0; ks < 8; ks++) {                                     \
        uint32_t afr[2][4];                                              \
        ldsm_x4(afr[0], (a_u32) + ks * 32);                              \
        ldsm_x4(afr[1], (a_u32) + 16 * A2_STRIDE * 4 + ks * 32);         \
        int p = ks * 4 + (t);                                            \
        int xs = xsw(p);                                                 \
        const uint32_t* wb = (sh_w) + p * 768;                           \
        _Pragma("unroll")                                                \
        for (int nt = 0; nt < 6; nt++) {                                 \
            int colb = (nt >> 1) * 128 + (wn) * 16 + (nt & 1) * 8;       \
            uint2 b2 = *(const uint2*)(wb + 2 * ((colb + (g)) ^ xs));    \
            mma16(acc[0][nt], afr[0], (const uint32_t*)&b2);             \
            mma16(acc[1][nt], afr[1], (const uint32_t*)&b2);             \
        }                                                                \
    }

// per-lane ldmatrix base offset (bytes) within an A buffer
__device__ __forceinline__ uint32_t ldsm_laneoff(int wm, int lane) {
    int rowL = wm * 32 + (lane & 7) + ((lane >> 3) & 1) * 8;
    int koffw = (lane >> 4) * 4;
    return (uint32_t)(rowL * A2_STRIDE + koffw) * 4;
}

// ======================================================================
// k_init (persistent): n_input = f_edges @ W_edge -> msg0 fp16 (+zero row 0);
//   gi = fp16(n_input @ W_ih^T + b_ih), stored in FRAGMENT ORDER:
//   gi[tile*12288 + tid*24 + (mt*2+i)*6 + gate*2 + q]
// ======================================================================
__global__ __launch_bounds__(512, 1) void k_init(
    const float* __restrict__ f_edges, const float* __restrict__ W_edge,
    const float* __restrict__ W_ih, const float* __restrict__ b_ih,
    __half* __restrict__ msg0, uint32_t* __restrict__ gi)
{
    extern __shared__ uint32_t smem_u[];
    uint32_t* sh_a16 = smem_u;                               // 4352 words
    uint32_t* sh_w   = smem_u + A2_WORDS;                    // 24576 words
    float* sh_we = (float*)(smem_u + A2_WORDS + W2_WORDS);   // 4096 floats
    float* sh_fe = sh_we + 4096;                             // 2048 floats

    const int tid = threadIdx.x;
    const int warp = tid >> 5, lane = tid & 31;
    const int wm = warp >> 3, wn = warp & 7;
    const int g = lane >> 2, t = lane & 3;

    load_w_full16(sh_w, W_ih, tid);
    for (int i = tid; i < 1024; i += 512)
        ((float4*)sh_we)[i] = ((const float4*)W_edge)[i];

    const uint32_t a_u32 = (uint32_t)__cvta_generic_to_shared(sh_a16) + ldsm_laneoff(wm, lane);

    // hoisted b_ih fragments
    float2 bi[3][2];
#pragma unroll
    for (int gate = 0; gate < 3; gate++)
#pragma unroll
        for (int q = 0; q < 2; q++)
            bi[gate][q] = *(const float2*)(b_ih + gate * 128 + wn * 16 + q * 8 + 2 * t);

    for (int tile = blockIdx.x; tile < NTILES; tile += gridDim.x) {
        const int e0 = tile * 64;

        ((float4*)sh_fe)[tid] = ((const float4*)(f_edges + (size_t)e0 * 32))[tid];
        __syncthreads();

        // n_input micro-GEMM
        float accv[4][4];
#pragma unroll
        for (int r = 0; r < 4; r++)
#pragma unroll
            for (int j = 0; j < 4; j++) accv[r][j] = 0.f;
#pragma unroll
        for (int k = 0; k < 32; k++) {
            float2 w0 = *(const float2*)(sh_we + k * 128 + 2 * lane);
            float2 w1 = *(const float2*)(sh_we + k * 128 + 64 + 2 * lane);
#pragma unroll
            for (int r = 0; r < 4; r++) {
                float f = sh_fe[(warp + 16 * r) * 32 + k];
                accv[r][0] += f * w0.x; accv[r][1] += f * w0.y;
                accv[r][2] += f * w1.x; accv[r][3] += f * w1.y;
            }
        }
#pragma unroll
        for (int r = 0; r < 4; r++) {
            int row = warp + 16 * r;
            int e = e0 + row;
            float v0 = accv[r][0], v1 = accv[r][1], v2 = accv[r][2], v3 = accv[r][3];
            if (e == 0) { v0 = v1 = v2 = v3 = 0.f; }
            uint32_t p0 = h2b(v0, v1), p1 = h2b(v2, v3);
            sh_a16[row * A2_STRIDE + lane]      = p0;
            sh_a16[row * A2_STRIDE + 32 + lane] = p1;
            *(uint32_t*)(msg0 + (size_t)e * 128 + 2 * lane)      = p0;
            *(uint32_t*)(msg0 + (size_t)e * 128 + 64 + 2 * lane) = p1;
        }
        __syncthreads();

        float acc[2][6][4];
#pragma unroll
        for (int a = 0; a < 2; a++)
#pragma unroll
            for (int b = 0; b < 6; b++)
#pragma unroll
                for (int c = 0; c < 4; c++) acc[a][b][c] = 0.f;

        GEMM_MAINLOOP16L(acc, a_u32, sh_w, wn, g, t)

        // epilogue: fragment-order gi, 6x STG.128 per thread
        uint32_t ow[24];
#pragma unroll
        for (int mt = 0; mt < 2; mt++)
#pragma unroll
            for (int i = 0; i < 2; i++)
#pragma unroll
                for (int gate = 0; gate < 3; gate++)
#pragma unroll
                    for (int q = 0; q < 2; q++) {
                        float ox = acc[mt][gate * 2 + q][2 * i]     + bi[gate][q].x;
                        float oy = acc[mt][gate * 2 + q][2 * i + 1] + bi[gate][q].y;
                        ow[(mt * 2 + i) * 6 + gate * 2 + q] = h2b(ox, oy);
                    }
        uint32_t* gdst = gi + (size_t)tile * 12288 + tid * 24;
#pragma unroll
        for (int kk = 0; kk < 6; kk++)
            *(uint4*)(gdst + kk * 4) = ((uint4*)ow)[kk];
        __syncthreads();
    }
}

// ======================================================================
// k_agg: a_message[n] = sum_{k<6} message[node2edge[n][k]]   (fp16 in/out)
// ======================================================================
__global__ __launch_bounds__(256) void k_agg(
    const __half* __restrict__ msg, const int* __restrict__ n2e,
    __half* __restrict__ amsg)
{
    int gid = blockIdx.x * 256 + threadIdx.x;
    int node = gid >> 5, lane = gid & 31;
    const int* ne = n2e + node * 6;
    float4 acc = {0.f, 0.f, 0.f, 0.f};
#pragma unroll
    for (int k = 0; k < 6; k++) {
        int e = __ldg(ne + k);
        uint2 v = ((const uint2*)(msg + (size_t)e * 128))[lane];
        float2 f0 = __half22float2(*(__half2*)&v.x);
        float2 f1 = __half22float2(*(__half2*)&v.y);
        acc.x += f0.x; acc.y += f0.y; acc.z += f1.x; acc.w += f1.y;
    }
    uint2 o;
    o.x = h2b(acc.x, acc.y);
    o.y = h2b(acc.z, acc.w);
    ((uint2*)(amsg + (size_t)node * 128))[lane] = o;
}

// gather h rows (fp16) into an A buffer
__device__ __forceinline__ void gather_h16(
    uint32_t* dst, const __half* __restrict__ amsg, const __half* __restrict__ msg_in,
    const int* __restrict__ edge2node, const int* __restrict__ b2revb,
    int e0, int row, int part)
{
    int e = e0 + row;
    int sn = __ldg(edge2node + e);
    int sr = __ldg(b2revb + e);
    const uint4* pa = (const uint4*)(amsg + (size_t)sn * 128) + part * 2;
    const uint4* pb = (const uint4*)(msg_in + (size_t)sr * 128) + part * 2;
#pragma unroll
    for (int c = 0; c < 2; c++) {
        uint4 va = pa[c], vb = pb[c];
        uint4 o;
        o.x = hsub2b(va.x, vb.x); o.y = hsub2b(va.y, vb.y);
        o.z = hsub2b(va.z, vb.z); o.w = hsub2b(va.w, vb.w);
        *(uint4*)(dst + row * A2_STRIDE + part * 8 + c * 4) = o;
    }
}

// ======================================================================
// k_step (persistent, double-buffered A, fp16 end-to-end)
// ======================================================================
__global__ __launch_bounds__(512, 1) void k_step(
    const __half* __restrict__ amsg, const __half* __restrict__ msg_in,
    const int* __restrict__ edge2node, const int* __restrict__ b2revb,
    const float* __restrict__ W_hh, const float* __restrict__ b_hh,
    const uint32_t* __restrict__ gi, __half* __restrict__ msg_out)
{
    extern __shared__ uint32_t smem_u[];
    uint32_t* sh_a0 = smem_u;
    uint32_t* sh_a1 = smem_u + A2_WORDS;
    uint32_t* sh_w  = smem_u + 2 * A2_WORDS;

    const int tid = threadIdx.x;
    const int warp = tid >> 5, lane = tid & 31;
    const int wm = warp >> 3, wn = warp & 7;
    const int g = lane >> 2, t = lane & 3;
    const int row = tid >> 3, part = tid & 7;

    load_w_full16(sh_w, W_hh, tid);

    const uint32_t lo = ldsm_laneoff(wm, lane);
    const uint32_t a0_u32 = (uint32_t)__cvta_generic_to_shared(sh_a0) + lo;
    const uint32_t a1_u32 = (uint32_t)__cvta_generic_to_shared(sh_a1) + lo;

    // hoisted b_hh fragments
    float2 bh[3][2];
#pragma unroll
    for (int gate = 0; gate < 3; gate++)
#pragma unroll
        for (int q = 0; q < 2; q++)
            bh[gate][q] = *(const float2*)(b_hh + gate * 128 + wn * 16 + q * 8 + 2 * t);

    const int jcol = wn * 16 + 2 * t;

    // prologue: gather first tile into buffer 0
    const int tile0 = blockIdx.x;
    gather_h16(sh_a0, amsg, msg_in, edge2node, b2revb, tile0 * 64, row, part);
    __syncthreads();

    int bufsel = 0;
    for (int tile = tile0; tile < NTILES; tile += gridDim.x) {
        const int e0 = tile * 64;
        uint32_t* cur = bufsel ? sh_a1 : sh_a0;
        uint32_t* nxt = bufsel ? sh_a0 : sh_a1;
        const uint32_t cur_u32 = bufsel ? a1_u32 : a0_u32;
        bufsel ^= 1;

        // ---- gi prefetch for THIS tile: 6 coalesced LDG.128 ----
        uint32_t gw[24];
        {
            const uint32_t* gsrc = gi + (size_t)tile * 12288 + tid * 24;
#pragma unroll
            for (int kk = 0; kk < 6; kk++)
                ((uint4*)gw)[kk] = *(const uint4*)(gsrc + kk * 4);
        }

        // ---- gather NEXT tile (overlaps GEMM) ----
        int ntile = tile + gridDim.x;
        if (ntile < NTILES)
            gather_h16(nxt, amsg, msg_in, edge2node, b2revb, ntile * 64, row, part);

        // ---- init acc: r,z gates = gi + b_hh ; n gate = 0 ----
        float acc[2][6][4];
#pragma unroll
        for (int mt = 0; mt < 2; mt++) {
#pragma unroll
            for (int i = 0; i < 2; i++) {
                int gb = (mt * 2 + i) * 6;
#pragma unroll
                for (int q = 0; q < 2; q++) {
                    float2 vr = __half22float2(*(__half2*)&gw[gb + q]);
                    acc[mt][q][2 * i]     = vr.x + bh[0][q].x;
                    acc[mt][q][2 * i + 1] = vr.y + bh[0][q].y;
                    float2 vz = __half22float2(*(__half2*)&gw[gb + 2 + q]);
                    acc[mt][2 + q][2 * i]     = vz.x + bh[1][q].x;
                    acc[mt][2 + q][2 * i + 1] = vz.y + bh[1][q].y;
                    acc[mt][4 + q][2 * i] = 0.f;
                    acc[mt][4 + q][2 * i + 1] = 0.f;
                }
            }
        }

        GEMM_MAINLOOP16L(acc, cur_u32, sh_w, wn, g, t)

        // GRU epilogue — no global loads
#pragma unroll
        for (int mt = 0; mt < 2; mt++) {
#pragma unroll
            for (int i = 0; i < 2; i++) {
                int erow = wm * 32 + mt * 16 + i * 8 + g;
                int e = e0 + erow;
                int gb = (mt * 2 + i) * 6;
#pragma unroll
                for (int q = 0; q < 2; q++) {
                    int j = jcol + q * 8;
                    float r0 = sigm(acc[mt][q][2 * i]);
                    float r1 = sigm(acc[mt][q][2 * i + 1]);
                    float z0 = sigm(acc[mt][2 + q][2 * i]);
                    float z1 = sigm(acc[mt][2 + q][2 * i + 1]);
                    float ghn0 = acc[mt][4 + q][2 * i]     + bh[2][q].x;
                    float ghn1 = acc[mt][4 + q][2 * i + 1] + bh[2][q].y;
                    float2 ginf = __half22float2(*(__half2*)&gw[gb + 4 + q]);
                    float n0 = fast_tanh(ginf.x + r0 * ghn0);
                    float n1 = fast_tanh(ginf.y + r1 * ghn1);
                    float2 hh = __half22float2(*(__half2*)(cur + erow * A2_STRIDE + (j >> 1)));
                    float o0 = (1.f - z0) * n0 + z0 * hh.x;
                    float o1 = (1.f - z1) * n1 + z1 * hh.y;
                    if (e == 0) { o0 = 0.f; o1 = 0.f; }
                    *(uint32_t*)(msg_out + (size_t)e * 128 + j) = h2b(o0, o1);
                }
            }
        }
        __syncthreads();   // nxt writes visible; cur reads done
    }
}

// ======================================================================
// k_readout: out = relu([emb[f_nodes], amsg] @ W_ro + b_ro)  (BM=64, BN=256, K=256)
// ======================================================================
__global__ __launch_bounds__(256) void k_readout(
    const int* __restrict__ f_nodes, const float* __restrict__ emb,
    const __half* __restrict__ amsg, const float* __restrict__ W_ro,
    const float* __restrict__ b_ro, float* __restrict__ out)
{
    extern __shared__ float smem[];
    float* sh_a = smem;                                     // 64 x RO_A_STRIDE
    uint32_t* sh_w = (uint32_t*)(smem + 64 * RO_A_STRIDE);  // 16 x RO_W_STRIDE

    const int tid = threadIdx.x;
    const int n0 = blockIdx.x * 64;

    {
        int row = tid >> 2, part = tid & 3;
        int n = n0 + row;
        bool valid = n < NN;
        int nc = valid ? n : (NN - 1);
        int tok = __ldg(f_nodes + nc);
        const float4* pe = (const float4*)(emb + (size_t)tok * 128);
        const uint2* pm = (const uint2*)(amsg + (size_t)nc * 128);
#pragma unroll
        for (int c = 0; c < 16; c++) {
            int c4 = part * 16 + c;
            float4 v;
            if (!valid) { v.x = v.y = v.z = v.w = 0.f; }
            else if (c4 < 32) v = pe[c4];
            else {
                uint2 hv = pm[c4 - 32];
                float2 f0 = __half22float2(*(__half2*)&hv.x);
                float2 f1 = __half22float2(*(__half2*)&hv.y);
                v.x = f0.x; v.y = f0.y; v.z = f1.x; v.w = f1.y;
            }
            *(float4*)(sh_a + row * RO_A_STRIDE + c4 * 4) = v;
        }
    }

    const int warp = tid >> 5, lane = tid & 31;
    const int wm = warp >> 2, wn = warp & 3;
    const int g = lane >> 2, t = lane & 3;

    float acc[2][8][4];
#pragma unroll
    for (int a = 0; a < 2; a++)
#pragma unroll
        for (int b = 0; b < 8; b++)
#pragma unroll
            for (int c = 0; c < 4; c++) acc[a][b][c] = 0.f;

    for (int kc = 0; kc < 256; kc += 32) {
        __syncthreads();
#pragma unroll
        for (int it = 0; it < 4; it++) {
            int i = tid + it * 256;
            int p = i >> 6, n4 = i & 63;
            int ks = p >> 2, tt = p & 3;
            const float* srcL = W_ro + (size_t)(kc + ks * 8 + tt) * 256 + n4 * 4;
            const float* srcH = W_ro + (size_t)(kc + ks * 8 + tt + 4) * 256 + n4 * 4;
            float4 lof = *(const float4*)srcL;
            float4 hif = *(const float4*)srcH;
            uint32_t* dst = sh_w + p * RO_W_STRIDE + n4 * 8;
            dst[0] = f2t(lof.x); dst[1] = f2t(hif.x);
            dst[2] = f2t(lof.y); dst[3] = f2t(hif.y);
            dst[4] = f2t(lof.z); dst[5] = f2t(hif.z);
            dst[6] = f2t(lof.w); dst[7] = f2t(hif.w);
        }
        __syncthreads();
#pragma unroll
        for (int ks = 0; ks < 4; ks++) {
            uint32_t afr[2][4];
#pragma unroll
            for (int mt = 0; mt < 2; mt++) {
                const float* base = sh_a + (wm * 32 + mt * 16 + g) * RO_A_STRIDE + kc + ks * 8 + t;
                afr[mt][0] = f2t(base[0]);
                afr[mt][1] = f2t(base[8 * RO_A_STRIDE]);
                afr[mt][2] = f2t(base[4]);
                afr[mt][3] = f2t(base[8 * RO_A_STRIDE + 4]);
            }
#pragma unroll
            for (int nt = 0; nt < 8; nt++) {
                int colb = wn * 64 + nt * 8;
                uint2 b2 = *(const uint2*)(sh_w + (ks * 4 + t) * RO_W_STRIDE + (colb + g) * 2);
                mma8(acc[0][nt], afr[0], (const uint32_t*)&b2);
                mma8(acc[1][nt], afr[1], (const uint32_t*)&b2);
            }
        }
    }

#pragma unroll
    for (int mt = 0; mt < 2; mt++) {
#pragma unroll
        for (int i = 0; i < 2; i++) {
            int row = wm * 32 + mt * 16 + i * 8 + g;
            int n = n0 + row;
            if (n >= NN) continue;
#pragma unroll
            for (int nt = 0; nt < 8; nt++) {
                int col = wn * 64 + nt * 8 + 2 * t;
                float2 br = *(const float2*)(b_ro + col);
                float2 o;
                o.x = fmaxf(acc[mt][nt][2 * i] + br.x, 0.f);
                o.y = fmaxf(acc[mt][nt][2 * i + 1] + br.y, 0.f);
                *(float2*)(out + (size_t)n * 256 + col) = o;
            }
        }
    }
}

// ======================================================================
extern "C" void kernel_launch(void* const* d_in, const int* in_sizes, int n_in,
                              void* d_out, int out_size)
{
    const int*   f_nodes   = (const int*)d_in[0];
    const float* f_edges   = (const float*)d_in[1];
    const int*   node2edge = (const int*)d_in[2];
    const int*   edge2node = (const int*)d_in[3];
    const int*   b2revb    = (const int*)d_in[4];
    const float* emb       = (const float*)d_in[5];
    const float* W_edge    = (const float*)d_in[6];
    const float* W_ih      = (const float*)d_in[7];
    const float* W_hh      = (const float*)d_in[8];
    const float* b_ih      = (const float*)d_in[9];
    const float* b_hh      = (const float*)d_in[10];
    const float* W_ro      = (const float*)d_in[11];
    const float* b_ro      = (const float*)d_in[12];
    float* outp = (float*)d_out;

    __half *msgA, *msgB, *amsgP;
    uint32_t* giP;
    cudaGetSymbolAddress((void**)&msgA, g_msgA);
    cudaGetSymbolAddress((void**)&msgB, g_msgB);
    cudaGetSymbolAddress((void**)&giP, g_gi);
    cudaGetSymbolAddress((void**)&amsgP, g_amsg);

    cudaFuncSetAttribute(k_init,    cudaFuncAttributeMaxDynamicSharedMemorySize, SMEM_INIT);
    cudaFuncSetAttribute(k_step,    cudaFuncAttributeMaxDynamicSharedMemorySize, SMEM_STEP);
    cudaFuncSetAttribute(k_readout, cudaFuncAttributeMaxDynamicSharedMemorySize, SMEM_RO);

    const int PGRID = 152;   // persistent: 1 CTA per SM (GB300 = 152 SMs)

    k_init<<<PGRID, 512, SMEM_INIT>>>(f_edges, W_edge, W_ih, b_ih, msgA, giP);
    k_nop<<<1, 32>>>();   // shifts ncu -s 5 capture onto k_step

    __half* cur = msgA;
    __half* nxt = msgB;
    for (int s = 0; s < 4; s++) {
        k_agg<<<(NN * 32) / 256, 256>>>(cur, node2edge, amsgP);
        k_step<<<PGRID, 512, SMEM_STEP>>>(amsgP, cur, edge2node, b2revb,
                                          W_hh, b_hh, giP, nxt);
        __half* tmp = cur; cur = nxt; nxt = tmp;
    }
    k_agg<<<(NN * 32) / 256, 256>>>(cur, node2edge, amsgP);
    k_readout<<<(NN + 63) / 64, 256, SMEM_RO>>>(f_nodes, emb, amsgP, W_ro, b_ro, outp);
}